// round 2
// baseline (speedup 1.0000x reference)
#include <cuda_runtime.h>
#include <math.h>

#define Bc  2
#define Tc  2048
#define Cc  1024
#define NHc 16
#define HDc 64

// Scratch (allocation-free rule: device globals)
__device__ float g_q[Bc * NHc * Tc * HDc];
__device__ float g_k[Bc * NHc * Tc * HDc];
__device__ float g_v[Bc * NHc * Tc * HDc];
__device__ float g_y[Bc * Tc * Cc];

// ---------------------------------------------------------------------------
// NT SGEMM:  O = A @ W^T
//   A [M,K] row-major, W [N,K] row-major.
//   SPLIT_HEADS: store O[m,n] at [b,h,t,d] (b=m/T, t=m%T, h=n/HD, d=n%HD)
// Tile 64x64, BK=16, 256 threads, 4x4 microtile per thread.
// ---------------------------------------------------------------------------
template <bool SPLIT_HEADS>
__global__ __launch_bounds__(256) void gemm_nt_kernel(
    const float* __restrict__ A, const float* __restrict__ W,
    float* __restrict__ O, int M, int N, int K)
{
    __shared__ float As[16][68];  // [k][m], padded
    __shared__ float Bs[16][68];  // [k][n], padded

    const int m0 = blockIdx.y * 64;
    const int n0 = blockIdx.x * 64;
    const int tid = threadIdx.x;
    const int tx = tid & 15;
    const int ty = tid >> 4;

    const int lr = tid >> 2;        // 0..63: row within tile to load
    const int lk = (tid & 3) << 2;  // 0,4,8,12: k offset to load

    const float* aptr = A + (size_t)(m0 + lr) * K + lk;
    const float* wptr = W + (size_t)(n0 + lr) * K + lk;

    float acc[4][4] = {};

    for (int k0 = 0; k0 < K; k0 += 16) {
        float4 av = *(const float4*)(aptr + k0);
        float4 wv = *(const float4*)(wptr + k0);
        As[lk + 0][lr] = av.x; As[lk + 1][lr] = av.y;
        As[lk + 2][lr] = av.z; As[lk + 3][lr] = av.w;
        Bs[lk + 0][lr] = wv.x; Bs[lk + 1][lr] = wv.y;
        Bs[lk + 2][lr] = wv.z; Bs[lk + 3][lr] = wv.w;
        __syncthreads();

        #pragma unroll
        for (int k = 0; k < 16; k++) {
            float ra[4], rb[4];
            #pragma unroll
            for (int i = 0; i < 4; i++) ra[i] = As[k][ty * 4 + i];
            #pragma unroll
            for (int j = 0; j < 4; j++) rb[j] = Bs[k][tx * 4 + j];
            #pragma unroll
            for (int i = 0; i < 4; i++)
                #pragma unroll
                for (int j = 0; j < 4; j++)
                    acc[i][j] = fmaf(ra[i], rb[j], acc[i][j]);
        }
        __syncthreads();
    }

    #pragma unroll
    for (int i = 0; i < 4; i++) {
        const int m = m0 + ty * 4 + i;
        #pragma unroll
        for (int j = 0; j < 4; j++) {
            const int n = n0 + tx * 4 + j;
            if (SPLIT_HEADS) {
                const int b = m / Tc, t = m % Tc, h = n / HDc, d = n % HDc;
                g_noop: ;
                O[(((size_t)b * NHc + h) * Tc + t) * HDc + d] = acc[i][j];
            } else {
                O[(size_t)m * N + n] = acc[i][j];
            }
        }
    }
}

// ---------------------------------------------------------------------------
// Causal flash attention, fp32, online softmax.
//   Q,K,V: [B,NH,T,HD]   Y: [B,T,C] (head-concatenated)
// One block per (q-tile of 64, head, batch). 256 threads, 4x4 microtiles.
// ---------------------------------------------------------------------------
__global__ __launch_bounds__(256) void attn_kernel(
    const float* __restrict__ Q, const float* __restrict__ K,
    const float* __restrict__ V, float* __restrict__ Y)
{
    const int TQ = 64, TK = 64;
    extern __shared__ float sm[];
    float (*Qs)[HDc + 1] = (float(*)[HDc + 1]) sm;                 // [64][65] r-major
    float (*Kst)[TK + 1] = (float(*)[TK + 1]) (sm + 64 * 65);      // [64][65] d-major (transposed)
    float (*Vs)[HDc + 1] = (float(*)[HDc + 1]) (sm + 2 * 64 * 65); // [64][65] c-major
    float (*Ps)[TK + 1]  = (float(*)[TK + 1]) (sm + 3 * 64 * 65);  // [64][65]

    const int qt = blockIdx.x, h = blockIdx.y, b = blockIdx.z;
    const int q0 = qt * TQ;
    const int tid = threadIdx.x;
    const int tx = tid & 15;
    const int ty = tid >> 4;
    const float scale = 0.125f;  // 1/sqrt(64)

    const float* Qb = Q + ((size_t)(b * NHc + h) * Tc + q0) * HDc;
    const float* Kb = K + ((size_t)(b * NHc + h) * Tc) * HDc;
    const float* Vb = V + ((size_t)(b * NHc + h) * Tc) * HDc;

    // Load Q tile (64x64): 1024 float4, 4 per thread
    #pragma unroll
    for (int it = 0; it < 4; it++) {
        const int i = tid + it * 256;
        const int r = i >> 4;
        const int c4 = (i & 15) << 2;
        float4 v = *(const float4*)(Qb + (size_t)r * HDc + c4);
        Qs[r][c4 + 0] = v.x; Qs[r][c4 + 1] = v.y;
        Qs[r][c4 + 2] = v.z; Qs[r][c4 + 3] = v.w;
    }

    float o[4][4] = {};
    float mrow[4], lrow[4];
    #pragma unroll
    for (int i = 0; i < 4; i++) { mrow[i] = -1e30f; lrow[i] = 0.0f; }

    for (int kt = 0; kt <= qt; kt++) {
        const int k0 = kt * TK;
        __syncthreads();  // prior PV reads of Ps/Vs done before overwrite

        // Load K (transposed to d-major) and V tiles
        #pragma unroll
        for (int it = 0; it < 4; it++) {
            const int i = tid + it * 256;
            const int r = i >> 4;
            const int c4 = (i & 15) << 2;
            float4 kv = *(const float4*)(Kb + (size_t)(k0 + r) * HDc + c4);
            Kst[c4 + 0][r] = kv.x; Kst[c4 + 1][r] = kv.y;
            Kst[c4 + 2][r] = kv.z; Kst[c4 + 3][r] = kv.w;
            float4 vv = *(const float4*)(Vb + (size_t)(k0 + r) * HDc + c4);
            Vs[r][c4 + 0] = vv.x; Vs[r][c4 + 1] = vv.y;
            Vs[r][c4 + 2] = vv.z; Vs[r][c4 + 3] = vv.w;
        }
        __syncthreads();

        // S = Q K^T  (4x4 microtile)
        float s[4][4] = {};
        #pragma unroll
        for (int d = 0; d < HDc; d++) {
            float ra[4], rb[4];
            #pragma unroll
            for (int i = 0; i < 4; i++) ra[i] = Qs[ty * 4 + i][d];
            #pragma unroll
            for (int j = 0; j < 4; j++) rb[j] = Kst[d][tx * 4 + j];
            #pragma unroll
            for (int i = 0; i < 4; i++)
                #pragma unroll
                for (int j = 0; j < 4; j++)
                    s[i][j] = fmaf(ra[i], rb[j], s[i][j]);
        }

        // Scale + causal mask (only diagonal tile needs masking)
        const bool diag = (kt == qt);
        #pragma unroll
        for (int i = 0; i < 4; i++)
            #pragma unroll
            for (int j = 0; j < 4; j++) {
                s[i][j] *= scale;
                if (diag && (k0 + tx * 4 + j > q0 + ty * 4 + i)) s[i][j] = -1e30f;
            }

        // Online softmax update per row (16 tx lanes share a row)
        #pragma unroll
        for (int i = 0; i < 4; i++) {
            float mx = s[i][0];
            #pragma unroll
            for (int j = 1; j < 4; j++) mx = fmaxf(mx, s[i][j]);
            mx = fmaxf(mx, __shfl_xor_sync(0xffffffffu, mx, 1));
            mx = fmaxf(mx, __shfl_xor_sync(0xffffffffu, mx, 2));
            mx = fmaxf(mx, __shfl_xor_sync(0xffffffffu, mx, 4));
            mx = fmaxf(mx, __shfl_xor_sync(0xffffffffu, mx, 8));
            const float mnew = fmaxf(mrow[i], mx);
            const float corr = __expf(mrow[i] - mnew);
            float ls = 0.0f;
            #pragma unroll
            for (int j = 0; j < 4; j++) {
                const float p = __expf(s[i][j] - mnew);
                Ps[ty * 4 + i][tx * 4 + j] = p;
                ls += p;
            }
            ls += __shfl_xor_sync(0xffffffffu, ls, 1);
            ls += __shfl_xor_sync(0xffffffffu, ls, 2);
            ls += __shfl_xor_sync(0xffffffffu, ls, 4);
            ls += __shfl_xor_sync(0xffffffffu, ls, 8);
            lrow[i] = lrow[i] * corr + ls;
            mrow[i] = mnew;
            #pragma unroll
            for (int j = 0; j < 4; j++) o[i][j] *= corr;
        }
        __syncthreads();

        // O += P @ V  (4x4 microtile)
        #pragma unroll
        for (int c = 0; c < TK; c++) {
            float pa[4], vb[4];
            #pragma unroll
            for (int i = 0; i < 4; i++) pa[i] = Ps[ty * 4 + i][c];
            #pragma unroll
            for (int j = 0; j < 4; j++) vb[j] = Vs[c][tx * 4 + j];
            #pragma unroll
            for (int i = 0; i < 4; i++)
                #pragma unroll
                for (int j = 0; j < 4; j++)
                    o[i][j] = fmaf(pa[i], vb[j], o[i][j]);
        }
    }

    // Write Y[b, q0+r, h*HD + d] = o / l
    float* Yb = Y + ((size_t)b * Tc + q0) * Cc + h * HDc;
    #pragma unroll
    for (int i = 0; i < 4; i++) {
        const float inv_l = 1.0f / lrow[i];
        #pragma unroll
        for (int j = 0; j < 4; j++)
            Yb[(size_t)(ty * 4 + i) * Cc + tx * 4 + j] = o[i][j] * inv_l;
    }
}

// ---------------------------------------------------------------------------
extern "C" void kernel_launch(void* const* d_in, const int* in_sizes, int n_in,
                              void* d_out, int out_size)
{
    const float* x  = (const float*)d_in[0];
    const float* Wq = (const float*)d_in[1];
    const float* Wk = (const float*)d_in[2];
    const float* Wv = (const float*)d_in[3];
    const float* Wo = (const float*)d_in[4];
    float* out = (float*)d_out;

    float *q, *k, *v, *y;
    cudaGetSymbolAddress((void**)&q, g_q);
    cudaGetSymbolAddress((void**)&k, g_k);
    cudaGetSymbolAddress((void**)&v, g_v);
    cudaGetSymbolAddress((void**)&y, g_y);

    const int M = Bc * Tc;  // 4096
    const dim3 ggrid(Cc / 64, M / 64);

    gemm_nt_kernel<true><<<ggrid, 256>>>(x, Wq, q, M, Cc, Cc);
    gemm_nt_kernel<true><<<ggrid, 256>>>(x, Wk, k, M, Cc, Cc);
    gemm_nt_kernel<true><<<ggrid, 256>>>(x, Wv, v, M, Cc, Cc);

    const int smem = 4 * 64 * 65 * (int)sizeof(float);  // 66560 B
    cudaFuncSetAttribute(attn_kernel, cudaFuncAttributeMaxDynamicSharedMemorySize, smem);
    attn_kernel<<<dim3(Tc / 64, NHc, Bc), 256, smem>>>(q, k, v, y);

    gemm_nt_kernel<false><<<ggrid, 256>>>(y, Wo, out, M, Cc, Cc);
}

// round 3
// speedup vs baseline: 1.0105x; 1.0105x over previous
#include <cuda_runtime.h>
#include <math.h>

#define Bc  2
#define Tc  2048
#define Cc  1024
#define NHc 16
#define HDc 64

// Scratch (allocation-free rule: device globals)
__device__ float g_q[Bc * NHc * Tc * HDc];
__device__ float g_k[Bc * NHc * Tc * HDc];
__device__ float g_v[Bc * NHc * Tc * HDc];
__device__ float g_y[Bc * Tc * Cc];

// ---------------------------------------------------------------------------
// NT SGEMM:  O = A @ W^T
//   A [M,K] row-major, W [N,K] row-major.
//   SPLIT_HEADS: store O[m,n] at [b,h,t,d] (b=m/T, t=m%T, h=n/HD, d=n%HD)
// Tile 64x64, BK=16, 256 threads, 4x4 microtile per thread.
// ---------------------------------------------------------------------------
template <bool SPLIT_HEADS>
__global__ __launch_bounds__(256) void gemm_nt_kernel(
    const float* __restrict__ A, const float* __restrict__ W,
    float* __restrict__ O, int M, int N, int K)
{
    __shared__ float As[16][68];  // [k][m], padded
    __shared__ float Bs[16][68];  // [k][n], padded

    const int m0 = blockIdx.y * 64;
    const int n0 = blockIdx.x * 64;
    const int tid = threadIdx.x;
    const int tx = tid & 15;
    const int ty = tid >> 4;

    const int lr = tid >> 2;        // 0..63: row within tile to load
    const int lk = (tid & 3) << 2;  // 0,4,8,12: k offset to load

    const float* aptr = A + (size_t)(m0 + lr) * K + lk;
    const float* wptr = W + (size_t)(n0 + lr) * K + lk;

    float acc[4][4] = {};

    for (int k0 = 0; k0 < K; k0 += 16) {
        float4 av = *(const float4*)(aptr + k0);
        float4 wv = *(const float4*)(wptr + k0);
        As[lk + 0][lr] = av.x; As[lk + 1][lr] = av.y;
        As[lk + 2][lr] = av.z; As[lk + 3][lr] = av.w;
        Bs[lk + 0][lr] = wv.x; Bs[lk + 1][lr] = wv.y;
        Bs[lk + 2][lr] = wv.z; Bs[lk + 3][lr] = wv.w;
        __syncthreads();

        #pragma unroll
        for (int k = 0; k < 16; k++) {
            float ra[4], rb[4];
            #pragma unroll
            for (int i = 0; i < 4; i++) ra[i] = As[k][ty * 4 + i];
            #pragma unroll
            for (int j = 0; j < 4; j++) rb[j] = Bs[k][tx * 4 + j];
            #pragma unroll
            for (int i = 0; i < 4; i++)
                #pragma unroll
                for (int j = 0; j < 4; j++)
                    acc[i][j] = fmaf(ra[i], rb[j], acc[i][j]);
        }
        __syncthreads();
    }

    #pragma unroll
    for (int i = 0; i < 4; i++) {
        const int m = m0 + ty * 4 + i;
        #pragma unroll
        for (int j = 0; j < 4; j++) {
            const int n = n0 + tx * 4 + j;
            if (SPLIT_HEADS) {
                const int b = m / Tc, t = m % Tc, h = n / HDc, d = n % HDc;
                g_noop: ;
                O[(((size_t)b * NHc + h) * Tc + t) * HDc + d] = acc[i][j];
            } else {
                O[(size_t)m * N + n] = acc[i][j];
            }
        }
    }
}

// ---------------------------------------------------------------------------
// Causal flash attention, fp32, online softmax.
//   Q,K,V: [B,NH,T,HD]   Y: [B,T,C] (head-concatenated)
// One block per (q-tile of 64, head, batch). 256 threads, 4x4 microtiles.
// ---------------------------------------------------------------------------
__global__ __launch_bounds__(256) void attn_kernel(
    const float* __restrict__ Q, const float* __restrict__ K,
    const float* __restrict__ V, float* __restrict__ Y)
{
    const int TQ = 64, TK = 64;
    extern __shared__ float sm[];
    float (*Qs)[HDc + 1] = (float(*)[HDc + 1]) sm;                 // [64][65] r-major
    float (*Kst)[TK + 1] = (float(*)[TK + 1]) (sm + 64 * 65);      // [64][65] d-major (transposed)
    float (*Vs)[HDc + 1] = (float(*)[HDc + 1]) (sm + 2 * 64 * 65); // [64][65] c-major
    float (*Ps)[TK + 1]  = (float(*)[TK + 1]) (sm + 3 * 64 * 65);  // [64][65]

    const int qt = blockIdx.x, h = blockIdx.y, b = blockIdx.z;
    const int q0 = qt * TQ;
    const int tid = threadIdx.x;
    const int tx = tid & 15;
    const int ty = tid >> 4;
    const float scale = 0.125f;  // 1/sqrt(64)

    const float* Qb = Q + ((size_t)(b * NHc + h) * Tc + q0) * HDc;
    const float* Kb = K + ((size_t)(b * NHc + h) * Tc) * HDc;
    const float* Vb = V + ((size_t)(b * NHc + h) * Tc) * HDc;

    // Load Q tile (64x64): 1024 float4, 4 per thread
    #pragma unroll
    for (int it = 0; it < 4; it++) {
        const int i = tid + it * 256;
        const int r = i >> 4;
        const int c4 = (i & 15) << 2;
        float4 v = *(const float4*)(Qb + (size_t)r * HDc + c4);
        Qs[r][c4 + 0] = v.x; Qs[r][c4 + 1] = v.y;
        Qs[r][c4 + 2] = v.z; Qs[r][c4 + 3] = v.w;
    }

    float o[4][4] = {};
    float mrow[4], lrow[4];
    #pragma unroll
    for (int i = 0; i < 4; i++) { mrow[i] = -1e30f; lrow[i] = 0.0f; }

    for (int kt = 0; kt <= qt; kt++) {
        const int k0 = kt * TK;
        __syncthreads();  // prior PV reads of Ps/Vs done before overwrite

        // Load K (transposed to d-major) and V tiles
        #pragma unroll
        for (int it = 0; it < 4; it++) {
            const int i = tid + it * 256;
            const int r = i >> 4;
            const int c4 = (i & 15) << 2;
            float4 kv = *(const float4*)(Kb + (size_t)(k0 + r) * HDc + c4);
            Kst[c4 + 0][r] = kv.x; Kst[c4 + 1][r] = kv.y;
            Kst[c4 + 2][r] = kv.z; Kst[c4 + 3][r] = kv.w;
            float4 vv = *(const float4*)(Vb + (size_t)(k0 + r) * HDc + c4);
            Vs[r][c4 + 0] = vv.x; Vs[r][c4 + 1] = vv.y;
            Vs[r][c4 + 2] = vv.z; Vs[r][c4 + 3] = vv.w;
        }
        __syncthreads();

        // S = Q K^T  (4x4 microtile)
        float s[4][4] = {};
        #pragma unroll
        for (int d = 0; d < HDc; d++) {
            float ra[4], rb[4];
            #pragma unroll
            for (int i = 0; i < 4; i++) ra[i] = Qs[ty * 4 + i][d];
            #pragma unroll
            for (int j = 0; j < 4; j++) rb[j] = Kst[d][tx * 4 + j];
            #pragma unroll
            for (int i = 0; i < 4; i++)
                #pragma unroll
                for (int j = 0; j < 4; j++)
                    s[i][j] = fmaf(ra[i], rb[j], s[i][j]);
        }

        // Scale + causal mask (only diagonal tile needs masking)
        const bool diag = (kt == qt);
        #pragma unroll
        for (int i = 0; i < 4; i++)
            #pragma unroll
            for (int j = 0; j < 4; j++) {
                s[i][j] *= scale;
                if (diag && (k0 + tx * 4 + j > q0 + ty * 4 + i)) s[i][j] = -1e30f;
            }

        // Online softmax update per row (16 tx lanes share a row)
        #pragma unroll
        for (int i = 0; i < 4; i++) {
            float mx = s[i][0];
            #pragma unroll
            for (int j = 1; j < 4; j++) mx = fmaxf(mx, s[i][j]);
            mx = fmaxf(mx, __shfl_xor_sync(0xffffffffu, mx, 1));
            mx = fmaxf(mx, __shfl_xor_sync(0xffffffffu, mx, 2));
            mx = fmaxf(mx, __shfl_xor_sync(0xffffffffu, mx, 4));
            mx = fmaxf(mx, __shfl_xor_sync(0xffffffffu, mx, 8));
            const float mnew = fmaxf(mrow[i], mx);
            const float corr = __expf(mrow[i] - mnew);
            float ls = 0.0f;
            #pragma unroll
            for (int j = 0; j < 4; j++) {
                const float p = __expf(s[i][j] - mnew);
                Ps[ty * 4 + i][tx * 4 + j] = p;
                ls += p;
            }
            ls += __shfl_xor_sync(0xffffffffu, ls, 1);
            ls += __shfl_xor_sync(0xffffffffu, ls, 2);
            ls += __shfl_xor_sync(0xffffffffu, ls, 4);
            ls += __shfl_xor_sync(0xffffffffu, ls, 8);
            lrow[i] = lrow[i] * corr + ls;
            mrow[i] = mnew;
            #pragma unroll
            for (int j = 0; j < 4; j++) o[i][j] *= corr;
        }
        __syncthreads();

        // O += P @ V  (4x4 microtile)
        #pragma unroll
        for (int c = 0; c < TK; c++) {
            float pa[4], vb[4];
            #pragma unroll
            for (int i = 0; i < 4; i++) pa[i] = Ps[ty * 4 + i][c];
            #pragma unroll
            for (int j = 0; j < 4; j++) vb[j] = Vs[c][tx * 4 + j];
            #pragma unroll
            for (int i = 0; i < 4; i++)
                #pragma unroll
                for (int j = 0; j < 4; j++)
                    o[i][j] = fmaf(pa[i], vb[j], o[i][j]);
        }
    }

    // Write Y[b, q0+r, h*HD + d] = o / l
    float* Yb = Y + ((size_t)b * Tc + q0) * Cc + h * HDc;
    #pragma unroll
    for (int i = 0; i < 4; i++) {
        const float inv_l = 1.0f / lrow[i];
        #pragma unroll
        for (int j = 0; j < 4; j++)
            Yb[(size_t)(ty * 4 + i) * Cc + tx * 4 + j] = o[i][j] * inv_l;
    }
}

// ---------------------------------------------------------------------------
extern "C" void kernel_launch(void* const* d_in, const int* in_sizes, int n_in,
                              void* d_out, int out_size)
{
    const float* x  = (const float*)d_in[0];
    const float* Wq = (const float*)d_in[1];
    const float* Wk = (const float*)d_in[2];
    const float* Wv = (const float*)d_in[3];
    const float* Wo = (const float*)d_in[4];
    float* out = (float*)d_out;

    float *q, *k, *v, *y;
    cudaGetSymbolAddress((void**)&q, g_q);
    cudaGetSymbolAddress((void**)&k, g_k);
    cudaGetSymbolAddress((void**)&v, g_v);
    cudaGetSymbolAddress((void**)&y, g_y);

    const int M = Bc * Tc;  // 4096
    const dim3 ggrid(Cc / 64, M / 64);

    gemm_nt_kernel<true><<<ggrid, 256>>>(x, Wq, q, M, Cc, Cc);
    gemm_nt_kernel<true><<<ggrid, 256>>>(x, Wk, k, M, Cc, Cc);
    gemm_nt_kernel<true><<<ggrid, 256>>>(x, Wv, v, M, Cc, Cc);

    const int smem = 4 * 64 * 65 * (int)sizeof(float);  // 66560 B
    cudaFuncSetAttribute(attn_kernel, cudaFuncAttributeMaxDynamicSharedMemorySize, smem);
    attn_kernel<<<dim3(Tc / 64, NHc, Bc), 256, smem>>>(q, k, v, y);

    gemm_nt_kernel<false><<<ggrid, 256>>>(y, Wo, out, M, Cc, Cc);
}

// round 4
// speedup vs baseline: 1.3483x; 1.3343x over previous
#include <cuda_runtime.h>
#include <cuda_bf16.h>
#include <mma.h>
#include <math.h>

using namespace nvcuda;

#define Bc  2
#define Tc  2048
#define Cc  1024
#define NHc 16
#define HDc 64

// ---------------- scratch (device globals; no allocation allowed) ----------
__device__ float g_q[Bc * NHc * Tc * HDc];
__device__ float g_k[Bc * NHc * Tc * HDc];
__device__ float g_v[Bc * NHc * Tc * HDc];
__device__ float g_y[Bc * Tc * Cc];

__device__ __nv_bfloat16 g_xhi[Bc * Tc * Cc];
__device__ __nv_bfloat16 g_xlo[Bc * Tc * Cc];
__device__ __nv_bfloat16 g_yhi[Bc * Tc * Cc];
__device__ __nv_bfloat16 g_ylo[Bc * Tc * Cc];
__device__ __nv_bfloat16 g_whi[4][Cc * Cc];
__device__ __nv_bfloat16 g_wlo[4][Cc * Cc];

// ---------------- fp32 -> bf16 hi/lo split ----------------------------------
__global__ __launch_bounds__(256) void split_kernel(
    const float* __restrict__ x, __nv_bfloat16* __restrict__ hi,
    __nv_bfloat16* __restrict__ lo, int n)
{
    int i = blockIdx.x * 256 + threadIdx.x;
    if (i < n) {
        float v = x[i];
        __nv_bfloat16 h = __float2bfloat16(v);
        hi[i] = h;
        lo[i] = __float2bfloat16(v - __bfloat162float(h));
    }
}

// ---------------- cp.async helpers ------------------------------------------
__device__ __forceinline__ void cp_async_16(void* smem, const void* gmem) {
    unsigned s = (unsigned)__cvta_generic_to_shared(smem);
    asm volatile("cp.async.cg.shared.global [%0], [%1], 16;\n" :: "r"(s), "l"(gmem));
}
__device__ __forceinline__ void cp_commit() {
    asm volatile("cp.async.commit_group;\n");
}
template <int N>
__device__ __forceinline__ void cp_wait() {
    asm volatile("cp.async.wait_group %0;\n" :: "n"(N));
}

// ---------------------------------------------------------------------------
// bf16x3 NT GEMM on tensor cores:  O = A @ W^T (fp32-accurate)
//   A given as (Ahi, Alo) [M,K] bf16 row-major; W as (Whi, Wlo) [N,K] bf16.
//   O fp32. SPLIT_HEADS: O[m,n] -> [b,h,t,d].
// CTA tile 128x128, BK=16, 8 warps (4x2), warp tile 32x64. 4-stage cp.async.
// ---------------------------------------------------------------------------
#define BM 128
#define BN 128
#define BK 16
#define STAGES 4
#define LDMH 24                       // padded halves per smem row (48B: conflict-free LDSM)
#define MAT_HALVES (128 * LDMH)       // 3072 halves per matrix tile
#define STAGE_HALVES (4 * MAT_HALVES) // Ahi,Alo,Whi,Wlo

template <bool SPLIT_HEADS>
__global__ __launch_bounds__(256) void gemm_bf16x3_kernel(
    const __nv_bfloat16* __restrict__ Ahi, const __nv_bfloat16* __restrict__ Alo,
    const __nv_bfloat16* __restrict__ Whi, const __nv_bfloat16* __restrict__ Wlo,
    float* __restrict__ O, int M, int N, int K)
{
    extern __shared__ __align__(16) __nv_bfloat16 sm[];

    const int tid = threadIdx.x;
    const int m0 = blockIdx.y * BM;
    const int n0 = blockIdx.x * BN;

    const int wid = tid >> 5;
    const int wm = wid & 3;   // 0..3 -> rows wm*32
    const int wn = wid >> 2;  // 0..1 -> cols wn*64

    // loader mapping: 2 threads per row (16B each)
    const int lrow = tid >> 1;
    const int lh8 = (tid & 1) * 8;

    const __nv_bfloat16* gAhi = Ahi + (size_t)(m0 + lrow) * K + lh8;
    const __nv_bfloat16* gAlo = Alo + (size_t)(m0 + lrow) * K + lh8;
    const __nv_bfloat16* gWhi = Whi + (size_t)(n0 + lrow) * K + lh8;
    const __nv_bfloat16* gWlo = Wlo + (size_t)(n0 + lrow) * K + lh8;
    __nv_bfloat16* sdst = sm + lrow * LDMH + lh8;

    const int nchunks = K / BK;  // 64

    auto load_stage = [&](int stage, int chunk) {
        __nv_bfloat16* base = sdst + stage * STAGE_HALVES;
        const int koff = chunk * BK;
        cp_async_16(base + 0 * MAT_HALVES, gAhi + koff);
        cp_async_16(base + 1 * MAT_HALVES, gAlo + koff);
        cp_async_16(base + 2 * MAT_HALVES, gWhi + koff);
        cp_async_16(base + 3 * MAT_HALVES, gWlo + koff);
        cp_commit();
    };

    #pragma unroll
    for (int s = 0; s < STAGES - 1; s++) load_stage(s, s);

    wmma::fragment<wmma::accumulator, 16, 16, 16, float> acc[2][4];
    #pragma unroll
    for (int i = 0; i < 2; i++)
        #pragma unroll
        for (int j = 0; j < 4; j++) wmma::fill_fragment(acc[i][j], 0.0f);

    for (int chunk = 0; chunk < nchunks; chunk++) {
        cp_wait<STAGES - 2>();
        __syncthreads();

        if (chunk + STAGES - 1 < nchunks)
            load_stage((chunk + STAGES - 1) % STAGES, chunk + STAGES - 1);

        const __nv_bfloat16* st = sm + (chunk % STAGES) * STAGE_HALVES;
        const __nv_bfloat16* sAhi = st + 0 * MAT_HALVES;
        const __nv_bfloat16* sAlo = st + 1 * MAT_HALVES;
        const __nv_bfloat16* sWhi = st + 2 * MAT_HALVES;
        const __nv_bfloat16* sWlo = st + 3 * MAT_HALVES;

        wmma::fragment<wmma::matrix_a, 16, 16, 16, __nv_bfloat16, wmma::row_major> ah[2], al[2];
        wmma::fragment<wmma::matrix_b, 16, 16, 16, __nv_bfloat16, wmma::col_major> bh[4], bl[4];

        #pragma unroll
        for (int i = 0; i < 2; i++) {
            wmma::load_matrix_sync(ah[i], sAhi + (wm * 32 + i * 16) * LDMH, LDMH);
            wmma::load_matrix_sync(al[i], sAlo + (wm * 32 + i * 16) * LDMH, LDMH);
        }
        #pragma unroll
        for (int j = 0; j < 4; j++) {
            wmma::load_matrix_sync(bh[j], sWhi + (wn * 64 + j * 16) * LDMH, LDMH);
            wmma::load_matrix_sync(bl[j], sWlo + (wn * 64 + j * 16) * LDMH, LDMH);
        }

        #pragma unroll
        for (int i = 0; i < 2; i++)
            #pragma unroll
            for (int j = 0; j < 4; j++) {
                wmma::mma_sync(acc[i][j], ah[i], bh[j], acc[i][j]);
                wmma::mma_sync(acc[i][j], ah[i], bl[j], acc[i][j]);
                wmma::mma_sync(acc[i][j], al[i], bh[j], acc[i][j]);
            }
        __syncthreads();
    }

    #pragma unroll
    for (int i = 0; i < 2; i++) {
        const int m = m0 + wm * 32 + i * 16;
        #pragma unroll
        for (int j = 0; j < 4; j++) {
            const int n = n0 + wn * 64 + j * 16;
            if (SPLIT_HEADS) {
                const int b = m / Tc, t = m % Tc, h = n / HDc, d = n % HDc;
                float* dst = O + (((size_t)b * NHc + h) * Tc + t) * HDc + d;
                wmma::store_matrix_sync(dst, acc[i][j], HDc, wmma::mem_row_major);
            } else {
                wmma::store_matrix_sync(O + (size_t)m * N + n, acc[i][j], N,
                                        wmma::mem_row_major);
            }
        }
    }
}

// ---------------------------------------------------------------------------
// Causal flash attention, fp32, online softmax (unchanged from R2).
// ---------------------------------------------------------------------------
__global__ __launch_bounds__(256) void attn_kernel(
    const float* __restrict__ Q, const float* __restrict__ K,
    const float* __restrict__ V, float* __restrict__ Y)
{
    const int TQ = 64, TK = 64;
    extern __shared__ float smf[];
    float (*Qs)[HDc + 1] = (float(*)[HDc + 1]) smf;
    float (*Kst)[TK + 1] = (float(*)[TK + 1]) (smf + 64 * 65);
    float (*Vs)[HDc + 1] = (float(*)[HDc + 1]) (smf + 2 * 64 * 65);
    float (*Ps)[TK + 1]  = (float(*)[TK + 1]) (smf + 3 * 64 * 65);

    const int qt = blockIdx.x, h = blockIdx.y, b = blockIdx.z;
    const int q0 = qt * TQ;
    const int tid = threadIdx.x;
    const int tx = tid & 15;
    const int ty = tid >> 4;
    const float scale = 0.125f;

    const float* Qb = Q + ((size_t)(b * NHc + h) * Tc + q0) * HDc;
    const float* Kb = K + ((size_t)(b * NHc + h) * Tc) * HDc;
    const float* Vb = V + ((size_t)(b * NHc + h) * Tc) * HDc;

    #pragma unroll
    for (int it = 0; it < 4; it++) {
        const int i = tid + it * 256;
        const int r = i >> 4;
        const int c4 = (i & 15) << 2;
        float4 v = *(const float4*)(Qb + (size_t)r * HDc + c4);
        Qs[r][c4 + 0] = v.x; Qs[r][c4 + 1] = v.y;
        Qs[r][c4 + 2] = v.z; Qs[r][c4 + 3] = v.w;
    }

    float o[4][4] = {};
    float mrow[4], lrow[4];
    #pragma unroll
    for (int i = 0; i < 4; i++) { mrow[i] = -1e30f; lrow[i] = 0.0f; }

    for (int kt = 0; kt <= qt; kt++) {
        const int k0 = kt * TK;
        __syncthreads();

        #pragma unroll
        for (int it = 0; it < 4; it++) {
            const int i = tid + it * 256;
            const int r = i >> 4;
            const int c4 = (i & 15) << 2;
            float4 kv = *(const float4*)(Kb + (size_t)(k0 + r) * HDc + c4);
            Kst[c4 + 0][r] = kv.x; Kst[c4 + 1][r] = kv.y;
            Kst[c4 + 2][r] = kv.z; Kst[c4 + 3][r] = kv.w;
            float4 vv = *(const float4*)(Vb + (size_t)(k0 + r) * HDc + c4);
            Vs[r][c4 + 0] = vv.x; Vs[r][c4 + 1] = vv.y;
            Vs[r][c4 + 2] = vv.z; Vs[r][c4 + 3] = vv.w;
        }
        __syncthreads();

        float s[4][4] = {};
        #pragma unroll
        for (int d = 0; d < HDc; d++) {
            float ra[4], rb[4];
            #pragma unroll
            for (int i = 0; i < 4; i++) ra[i] = Qs[ty * 4 + i][d];
            #pragma unroll
            for (int j = 0; j < 4; j++) rb[j] = Kst[d][tx * 4 + j];
            #pragma unroll
            for (int i = 0; i < 4; i++)
                #pragma unroll
                for (int j = 0; j < 4; j++)
                    s[i][j] = fmaf(ra[i], rb[j], s[i][j]);
        }

        const bool diag = (kt == qt);
        #pragma unroll
        for (int i = 0; i < 4; i++)
            #pragma unroll
            for (int j = 0; j < 4; j++) {
                s[i][j] *= scale;
                if (diag && (k0 + tx * 4 + j > q0 + ty * 4 + i)) s[i][j] = -1e30f;
            }

        #pragma unroll
        for (int i = 0; i < 4; i++) {
            float mx = s[i][0];
            #pragma unroll
            for (int j = 1; j < 4; j++) mx = fmaxf(mx, s[i][j]);
            mx = fmaxf(mx, __shfl_xor_sync(0xffffffffu, mx, 1));
            mx = fmaxf(mx, __shfl_xor_sync(0xffffffffu, mx, 2));
            mx = fmaxf(mx, __shfl_xor_sync(0xffffffffu, mx, 4));
            mx = fmaxf(mx, __shfl_xor_sync(0xffffffffu, mx, 8));
            const float mnew = fmaxf(mrow[i], mx);
            const float corr = __expf(mrow[i] - mnew);
            float ls = 0.0f;
            #pragma unroll
            for (int j = 0; j < 4; j++) {
                const float p = __expf(s[i][j] - mnew);
                Ps[ty * 4 + i][tx * 4 + j] = p;
                ls += p;
            }
            ls += __shfl_xor_sync(0xffffffffu, ls, 1);
            ls += __shfl_xor_sync(0xffffffffu, ls, 2);
            ls += __shfl_xor_sync(0xffffffffu, ls, 4);
            ls += __shfl_xor_sync(0xffffffffu, ls, 8);
            lrow[i] = lrow[i] * corr + ls;
            mrow[i] = mnew;
            #pragma unroll
            for (int j = 0; j < 4; j++) o[i][j] *= corr;
        }
        __syncthreads();

        #pragma unroll
        for (int c = 0; c < TK; c++) {
            float pa[4], vb[4];
            #pragma unroll
            for (int i = 0; i < 4; i++) pa[i] = Ps[ty * 4 + i][c];
            #pragma unroll
            for (int j = 0; j < 4; j++) vb[j] = Vs[c][tx * 4 + j];
            #pragma unroll
            for (int i = 0; i < 4; i++)
                #pragma unroll
                for (int j = 0; j < 4; j++)
                    o[i][j] = fmaf(pa[i], vb[j], o[i][j]);
        }
    }

    float* Yb = Y + ((size_t)b * Tc + q0) * Cc + h * HDc;
    #pragma unroll
    for (int i = 0; i < 4; i++) {
        const float inv_l = 1.0f / lrow[i];
        #pragma unroll
        for (int j = 0; j < 4; j++)
            Yb[(size_t)(ty * 4 + i) * Cc + tx * 4 + j] = o[i][j] * inv_l;
    }
}

// ---------------------------------------------------------------------------
extern "C" void kernel_launch(void* const* d_in, const int* in_sizes, int n_in,
                              void* d_out, int out_size)
{
    const float* x  = (const float*)d_in[0];
    const float* Wq = (const float*)d_in[1];
    const float* Wk = (const float*)d_in[2];
    const float* Wv = (const float*)d_in[3];
    const float* Wo = (const float*)d_in[4];
    float* out = (float*)d_out;

    float *q, *k, *v, *y;
    cudaGetSymbolAddress((void**)&q, g_q);
    cudaGetSymbolAddress((void**)&k, g_k);
    cudaGetSymbolAddress((void**)&v, g_v);
    cudaGetSymbolAddress((void**)&y, g_y);

    __nv_bfloat16 *xhi, *xlo, *yhi, *ylo, *whi, *wlo;
    cudaGetSymbolAddress((void**)&xhi, g_xhi);
    cudaGetSymbolAddress((void**)&xlo, g_xlo);
    cudaGetSymbolAddress((void**)&yhi, g_yhi);
    cudaGetSymbolAddress((void**)&ylo, g_ylo);
    cudaGetSymbolAddress((void**)&whi, g_whi);
    cudaGetSymbolAddress((void**)&wlo, g_wlo);

    const int M = Bc * Tc;       // 4096
    const int NELX = M * Cc;     // 4 M
    const int NELW = Cc * Cc;    // 1 M

    // fp32 -> bf16 hi/lo splits
    split_kernel<<<(NELX + 255) / 256, 256>>>(x, xhi, xlo, NELX);
    split_kernel<<<(NELW + 255) / 256, 256>>>(Wq, whi + 0 * NELW, wlo + 0 * NELW, NELW);
    split_kernel<<<(NELW + 255) / 256, 256>>>(Wk, whi + 1 * NELW, wlo + 1 * NELW, NELW);
    split_kernel<<<(NELW + 255) / 256, 256>>>(Wv, whi + 2 * NELW, wlo + 2 * NELW, NELW);
    split_kernel<<<(NELW + 255) / 256, 256>>>(Wo, whi + 3 * NELW, wlo + 3 * NELW, NELW);

    const dim3 ggrid(Cc / BN, M / BM);  // (8, 32)
    const int gsmem = STAGES * STAGE_HALVES * (int)sizeof(__nv_bfloat16);  // 96 KB

    cudaFuncSetAttribute(gemm_bf16x3_kernel<true>,
                         cudaFuncAttributeMaxDynamicSharedMemorySize, gsmem);
    cudaFuncSetAttribute(gemm_bf16x3_kernel<false>,
                         cudaFuncAttributeMaxDynamicSharedMemorySize, gsmem);

    gemm_bf16x3_kernel<true><<<ggrid, 256, gsmem>>>(xhi, xlo, whi + 0 * NELW, wlo + 0 * NELW, q, M, Cc, Cc);
    gemm_bf16x3_kernel<true><<<ggrid, 256, gsmem>>>(xhi, xlo, whi + 1 * NELW, wlo + 1 * NELW, k, M, Cc, Cc);
    gemm_bf16x3_kernel<true><<<ggrid, 256, gsmem>>>(xhi, xlo, whi + 2 * NELW, wlo + 2 * NELW, v, M, Cc, Cc);

    const int asmem = 4 * 64 * 65 * (int)sizeof(float);  // 66560 B
    cudaFuncSetAttribute(attn_kernel, cudaFuncAttributeMaxDynamicSharedMemorySize, asmem);
    attn_kernel<<<dim3(Tc / 64, NHc, Bc), 256, asmem>>>(q, k, v, y);

    split_kernel<<<(NELX + 255) / 256, 256>>>(y, yhi, ylo, NELX);
    gemm_bf16x3_kernel<false><<<ggrid, 256, gsmem>>>(yhi, ylo, whi + 3 * NELW, wlo + 3 * NELW, out, M, Cc, Cc);
}

// round 5
// speedup vs baseline: 1.8914x; 1.4028x over previous
#include <cuda_runtime.h>
#include <cuda_bf16.h>
#include <mma.h>
#include <math.h>

using namespace nvcuda;

#define Bc  2
#define Tc  2048
#define Cc  1024
#define NHc 16
#define HDc 64

// ---------------- scratch (device globals; no allocation allowed) ----------
__device__ __nv_bfloat16 g_qhi[Bc * NHc * Tc * HDc];
__device__ __nv_bfloat16 g_qlo[Bc * NHc * Tc * HDc];
__device__ __nv_bfloat16 g_khi[Bc * NHc * Tc * HDc];
__device__ __nv_bfloat16 g_klo[Bc * NHc * Tc * HDc];
__device__ __nv_bfloat16 g_vhi[Bc * NHc * Tc * HDc];
__device__ __nv_bfloat16 g_vlo[Bc * NHc * Tc * HDc];
__device__ __nv_bfloat16 g_xhi[Bc * Tc * Cc];
__device__ __nv_bfloat16 g_xlo[Bc * Tc * Cc];
__device__ __nv_bfloat16 g_yhi[Bc * Tc * Cc];
__device__ __nv_bfloat16 g_ylo[Bc * Tc * Cc];
__device__ __nv_bfloat16 g_whi[4][Cc * Cc];
__device__ __nv_bfloat16 g_wlo[4][Cc * Cc];

// ---------------- fp32 -> bf16 hi/lo split (4 elems/thread) -----------------
__global__ __launch_bounds__(256) void split_kernel(
    const float* __restrict__ x, __nv_bfloat16* __restrict__ hi,
    __nv_bfloat16* __restrict__ lo, int n4)
{
    int i = blockIdx.x * 256 + threadIdx.x;
    if (i < n4) {
        float4 v = ((const float4*)x)[i];
        __nv_bfloat16 h0 = __float2bfloat16(v.x), h1 = __float2bfloat16(v.y);
        __nv_bfloat16 h2 = __float2bfloat16(v.z), h3 = __float2bfloat16(v.w);
        __nv_bfloat162* hp = (__nv_bfloat162*)(hi + i * 4);
        __nv_bfloat162* lp = (__nv_bfloat162*)(lo + i * 4);
        hp[0] = __nv_bfloat162(h0, h1);
        hp[1] = __nv_bfloat162(h2, h3);
        lp[0] = __nv_bfloat162(__float2bfloat16(v.x - __bfloat162float(h0)),
                               __float2bfloat16(v.y - __bfloat162float(h1)));
        lp[1] = __nv_bfloat162(__float2bfloat16(v.z - __bfloat162float(h2)),
                               __float2bfloat16(v.w - __bfloat162float(h3)));
    }
}

// ---------------- cp.async helpers ------------------------------------------
__device__ __forceinline__ void cp_async_16(void* smem, const void* gmem) {
    unsigned s = (unsigned)__cvta_generic_to_shared(smem);
    asm volatile("cp.async.cg.shared.global [%0], [%1], 16;\n" :: "r"(s), "l"(gmem));
}
__device__ __forceinline__ void cp_commit() {
    asm volatile("cp.async.commit_group;\n");
}
template <int N>
__device__ __forceinline__ void cp_wait() {
    asm volatile("cp.async.wait_group %0;\n" :: "n"(N));
}

// ---------------------------------------------------------------------------
// bf16x3 NT GEMM:  O = sc * (A @ W^T)
// MODE 0: fp32 direct store [M,N].  MODE 1: split-heads, bf16 hi/lo output.
// CTA tile 128x128, BK=16, 8 warps, 4-stage cp.async.
// ---------------------------------------------------------------------------
#define BM 128
#define BN 128
#define BK 16
#define STAGES 4
#define LDMH 24
#define MAT_HALVES (128 * LDMH)
#define STAGE_HALVES (4 * MAT_HALVES)
#define GSMEM_BYTES (STAGES * STAGE_HALVES * 2)  // 98304

template <int MODE>
__global__ __launch_bounds__(256) void gemm_bf16x3_kernel(
    const __nv_bfloat16* __restrict__ Ahi, const __nv_bfloat16* __restrict__ Alo,
    const __nv_bfloat16* __restrict__ Whi, const __nv_bfloat16* __restrict__ Wlo,
    float* __restrict__ O, __nv_bfloat16* __restrict__ Ohi,
    __nv_bfloat16* __restrict__ Olo, float sc, int M, int N, int K)
{
    extern __shared__ __align__(16) __nv_bfloat16 sm[];

    const int tid = threadIdx.x;
    const int m0 = blockIdx.y * BM;
    const int n0 = blockIdx.x * BN;

    const int wid = tid >> 5;
    const int wm = wid & 3;
    const int wn = wid >> 2;

    const int lrow = tid >> 1;
    const int lh8 = (tid & 1) * 8;

    const __nv_bfloat16* gAhi = Ahi + (size_t)(m0 + lrow) * K + lh8;
    const __nv_bfloat16* gAlo = Alo + (size_t)(m0 + lrow) * K + lh8;
    const __nv_bfloat16* gWhi = Whi + (size_t)(n0 + lrow) * K + lh8;
    const __nv_bfloat16* gWlo = Wlo + (size_t)(n0 + lrow) * K + lh8;
    __nv_bfloat16* sdst = sm + lrow * LDMH + lh8;

    const int nchunks = K / BK;

    auto load_stage = [&](int stage, int chunk) {
        __nv_bfloat16* base = sdst + stage * STAGE_HALVES;
        const int koff = chunk * BK;
        cp_async_16(base + 0 * MAT_HALVES, gAhi + koff);
        cp_async_16(base + 1 * MAT_HALVES, gAlo + koff);
        cp_async_16(base + 2 * MAT_HALVES, gWhi + koff);
        cp_async_16(base + 3 * MAT_HALVES, gWlo + koff);
        cp_commit();
    };

    #pragma unroll
    for (int s = 0; s < STAGES - 1; s++) load_stage(s, s);

    wmma::fragment<wmma::accumulator, 16, 16, 16, float> acc[2][4];
    #pragma unroll
    for (int i = 0; i < 2; i++)
        #pragma unroll
        for (int j = 0; j < 4; j++) wmma::fill_fragment(acc[i][j], 0.0f);

    for (int chunk = 0; chunk < nchunks; chunk++) {
        cp_wait<STAGES - 2>();
        __syncthreads();

        if (chunk + STAGES - 1 < nchunks)
            load_stage((chunk + STAGES - 1) % STAGES, chunk + STAGES - 1);

        const __nv_bfloat16* st = sm + (chunk % STAGES) * STAGE_HALVES;
        const __nv_bfloat16* sAhi = st + 0 * MAT_HALVES;
        const __nv_bfloat16* sAlo = st + 1 * MAT_HALVES;
        const __nv_bfloat16* sWhi = st + 2 * MAT_HALVES;
        const __nv_bfloat16* sWlo = st + 3 * MAT_HALVES;

        wmma::fragment<wmma::matrix_a, 16, 16, 16, __nv_bfloat16, wmma::row_major> ah[2], al[2];
        wmma::fragment<wmma::matrix_b, 16, 16, 16, __nv_bfloat16, wmma::col_major> bh[4], bl[4];

        #pragma unroll
        for (int i = 0; i < 2; i++) {
            wmma::load_matrix_sync(ah[i], sAhi + (wm * 32 + i * 16) * LDMH, LDMH);
            wmma::load_matrix_sync(al[i], sAlo + (wm * 32 + i * 16) * LDMH, LDMH);
        }
        #pragma unroll
        for (int j = 0; j < 4; j++) {
            wmma::load_matrix_sync(bh[j], sWhi + (wn * 64 + j * 16) * LDMH, LDMH);
            wmma::load_matrix_sync(bl[j], sWlo + (wn * 64 + j * 16) * LDMH, LDMH);
        }

        #pragma unroll
        for (int i = 0; i < 2; i++)
            #pragma unroll
            for (int j = 0; j < 4; j++) {
                wmma::mma_sync(acc[i][j], ah[i], bh[j], acc[i][j]);
                wmma::mma_sync(acc[i][j], ah[i], bl[j], acc[i][j]);
                wmma::mma_sync(acc[i][j], al[i], bh[j], acc[i][j]);
            }
        __syncthreads();
    }

    if (MODE == 0) {
        #pragma unroll
        for (int i = 0; i < 2; i++) {
            const int m = m0 + wm * 32 + i * 16;
            #pragma unroll
            for (int j = 0; j < 4; j++) {
                const int n = n0 + wn * 64 + j * 16;
                wmma::store_matrix_sync(O + (size_t)m * N + n, acc[i][j], N,
                                        wmma::mem_row_major);
            }
        }
    } else {
        // stage to smem fp32, then scale + hi/lo split + scatter to [b,h,t,d]
        __syncthreads();
        float* sf = (float*)sm;  // 128 x 132
        #pragma unroll
        for (int i = 0; i < 2; i++)
            #pragma unroll
            for (int j = 0; j < 4; j++)
                wmma::store_matrix_sync(sf + (wm * 32 + i * 16) * 132 + wn * 64 + j * 16,
                                        acc[i][j], 132, wmma::mem_row_major);
        __syncthreads();

        #pragma unroll
        for (int it = 0; it < 16; it++) {
            const int idx = tid + it * 256;
            const int r = idx >> 5;
            const int c4 = (idx & 31) << 2;
            float4 v = *(const float4*)(sf + r * 132 + c4);
            const int m = m0 + r, n = n0 + c4;
            const int b = m >> 11, t = m & 2047, h = n >> 6, d = n & 63;
            const size_t off = (((size_t)(b * NHc + h) * Tc + t) * HDc + d);
            float f0 = v.x * sc, f1 = v.y * sc, f2 = v.z * sc, f3 = v.w * sc;
            __nv_bfloat16 h0 = __float2bfloat16(f0), h1 = __float2bfloat16(f1);
            __nv_bfloat16 h2 = __float2bfloat16(f2), h3 = __float2bfloat16(f3);
            __nv_bfloat162* hp = (__nv_bfloat162*)(Ohi + off);
            __nv_bfloat162* lp = (__nv_bfloat162*)(Olo + off);
            hp[0] = __nv_bfloat162(h0, h1);
            hp[1] = __nv_bfloat162(h2, h3);
            lp[0] = __nv_bfloat162(__float2bfloat16(f0 - __bfloat162float(h0)),
                                   __float2bfloat16(f1 - __bfloat162float(h1)));
            lp[1] = __nv_bfloat162(__float2bfloat16(f2 - __bfloat162float(h2)),
                                   __float2bfloat16(f3 - __bfloat162float(h3)));
        }
    }
}

// ---------------------------------------------------------------------------
// Tensor-core causal flash attention (bf16x3, fp32 softmax/accum).
// 64q x 64k tiles, 8 warps (warp = 16q-strip x 32k-half), 256 threads.
// Q pre-scaled by 0.125 in the GEMM epilogue.
// ---------------------------------------------------------------------------
#define AK_LD 72                       // bf16 tile leading dim (halves)
#define AS_LD 68                       // fp32 tile leading dim (floats)
#define AOFF_KH 0
#define AOFF_KL 9216
#define AOFF_VH 18432
#define AOFF_VL 27648
#define AOFF_S  36864
#define AOFF_PH 54272
#define AOFF_PL 63488
#define AOFF_O  72704
#define ASMEM_BYTES 90112

__global__ __launch_bounds__(256) void attn_tc_kernel(
    const __nv_bfloat16* __restrict__ Qhi, const __nv_bfloat16* __restrict__ Qlo,
    const __nv_bfloat16* __restrict__ Khi_g, const __nv_bfloat16* __restrict__ Klo_g,
    const __nv_bfloat16* __restrict__ Vhi_g, const __nv_bfloat16* __restrict__ Vlo_g,
    __nv_bfloat16* __restrict__ Yhi, __nv_bfloat16* __restrict__ Ylo)
{
    extern __shared__ __align__(16) char asm_[];
    __nv_bfloat16* sKh = (__nv_bfloat16*)(asm_ + AOFF_KH);
    __nv_bfloat16* sKl = (__nv_bfloat16*)(asm_ + AOFF_KL);
    __nv_bfloat16* sVh = (__nv_bfloat16*)(asm_ + AOFF_VH);
    __nv_bfloat16* sVl = (__nv_bfloat16*)(asm_ + AOFF_VL);
    float*         sS  = (float*)(asm_ + AOFF_S);
    __nv_bfloat16* sPh = (__nv_bfloat16*)(asm_ + AOFF_PH);
    __nv_bfloat16* sPl = (__nv_bfloat16*)(asm_ + AOFF_PL);
    float*         sO  = (float*)(asm_ + AOFF_O);

    const int qt = blockIdx.x, h = blockIdx.y, b = blockIdx.z;
    const int q0 = qt * 64;
    const int tid = threadIdx.x;
    const int wid = tid >> 5;
    const int sr = wid >> 1;            // q strip: rows sr*16
    const int scw = wid & 1;            // k/d half: cols scw*32

    const size_t bh = (size_t)(b * NHc + h) * Tc;
    const __nv_bfloat16* qhb = Qhi + (bh + q0) * HDc;
    const __nv_bfloat16* qlb = Qlo + (bh + q0) * HDc;

    // --- stage Q into K buffers and load persistent A-fragments -------------
    #pragma unroll
    for (int it = 0; it < 2; it++) {
        const int idx = tid + it * 256;
        const int r = idx >> 3;
        const int c8 = (idx & 7) * 8;
        *(uint4*)(sKh + r * AK_LD + c8) = *(const uint4*)(qhb + (size_t)r * HDc + c8);
        *(uint4*)(sKl + r * AK_LD + c8) = *(const uint4*)(qlb + (size_t)r * HDc + c8);
    }
    // zero O accumulator (thread owns row r = tid>>2, cols (tid&3)*16..+15)
    {
        const int r = tid >> 2, cq = (tid & 3) * 16;
        #pragma unroll
        for (int i = 0; i < 4; i++)
            *(float4*)(sO + r * AS_LD + cq + i * 4) = make_float4(0.f, 0.f, 0.f, 0.f);
    }
    __syncthreads();

    wmma::fragment<wmma::matrix_a, 16, 16, 16, __nv_bfloat16, wmma::row_major> qh[4], ql[4];
    #pragma unroll
    for (int ks = 0; ks < 4; ks++) {
        wmma::load_matrix_sync(qh[ks], sKh + (sr * 16) * AK_LD + ks * 16, AK_LD);
        wmma::load_matrix_sync(ql[ks], sKl + (sr * 16) * AK_LD + ks * 16, AK_LD);
    }

    const int r = tid >> 2;
    const int cq = (tid & 3) * 16;
    float mrow = -1e30f, lrow = 0.0f;

    const __nv_bfloat16* khb = Khi_g + bh * HDc;
    const __nv_bfloat16* klb = Klo_g + bh * HDc;
    const __nv_bfloat16* vhb = Vhi_g + bh * HDc;
    const __nv_bfloat16* vlb = Vlo_g + bh * HDc;

    for (int kt = 0; kt <= qt; kt++) {
        const int k0 = kt * 64;
        __syncthreads();

        // load K,V hi/lo tiles
        #pragma unroll
        for (int it = 0; it < 2; it++) {
            const int idx = tid + it * 256;
            const int rr = idx >> 3;
            const int c8 = (idx & 7) * 8;
            const size_t g = (size_t)(k0 + rr) * HDc + c8;
            *(uint4*)(sKh + rr * AK_LD + c8) = *(const uint4*)(khb + g);
            *(uint4*)(sKl + rr * AK_LD + c8) = *(const uint4*)(klb + g);
            *(uint4*)(sVh + rr * AK_LD + c8) = *(const uint4*)(vhb + g);
            *(uint4*)(sVl + rr * AK_LD + c8) = *(const uint4*)(vlb + g);
        }
        __syncthreads();

        // --- S = Q K^T (bf16x3) ---------------------------------------------
        {
            wmma::fragment<wmma::accumulator, 16, 16, 16, float> sacc[2];
            wmma::fill_fragment(sacc[0], 0.0f);
            wmma::fill_fragment(sacc[1], 0.0f);
            #pragma unroll
            for (int ks = 0; ks < 4; ks++) {
                #pragma unroll
                for (int t = 0; t < 2; t++) {
                    wmma::fragment<wmma::matrix_b, 16, 16, 16, __nv_bfloat16, wmma::col_major> bh_, bl_;
                    const int nb = (scw * 32 + t * 16);
                    wmma::load_matrix_sync(bh_, sKh + nb * AK_LD + ks * 16, AK_LD);
                    wmma::load_matrix_sync(bl_, sKl + nb * AK_LD + ks * 16, AK_LD);
                    wmma::mma_sync(sacc[t], qh[ks], bh_, sacc[t]);
                    wmma::mma_sync(sacc[t], qh[ks], bl_, sacc[t]);
                    wmma::mma_sync(sacc[t], ql[ks], bh_, sacc[t]);
                }
            }
            #pragma unroll
            for (int t = 0; t < 2; t++)
                wmma::store_matrix_sync(sS + (sr * 16) * AS_LD + scw * 32 + t * 16,
                                        sacc[t], AS_LD, wmma::mem_row_major);
        }
        __syncthreads();

        // --- softmax (4 threads per row) + O rescale -------------------------
        {
            float sv[16];
            #pragma unroll
            for (int i = 0; i < 4; i++) {
                float4 v = *(const float4*)(sS + r * AS_LD + cq + i * 4);
                sv[i * 4 + 0] = v.x; sv[i * 4 + 1] = v.y;
                sv[i * 4 + 2] = v.z; sv[i * 4 + 3] = v.w;
            }
            if (kt == qt) {
                #pragma unroll
                for (int j = 0; j < 16; j++)
                    if (cq + j > r) sv[j] = -1e30f;
            }
            float mx = sv[0];
            #pragma unroll
            for (int j = 1; j < 16; j++) mx = fmaxf(mx, sv[j]);
            mx = fmaxf(mx, __shfl_xor_sync(0xffffffffu, mx, 1));
            mx = fmaxf(mx, __shfl_xor_sync(0xffffffffu, mx, 2));
            const float mnew = fmaxf(mrow, mx);
            const float corr = __expf(mrow - mnew);
            float ls = 0.0f;
            #pragma unroll
            for (int j = 0; j < 16; j += 2) {
                const float p0 = __expf(sv[j] - mnew);
                const float p1 = __expf(sv[j + 1] - mnew);
                ls += p0 + p1;
                const __nv_bfloat16 h0 = __float2bfloat16(p0);
                const __nv_bfloat16 h1 = __float2bfloat16(p1);
                *(__nv_bfloat162*)(sPh + r * AK_LD + cq + j) = __nv_bfloat162(h0, h1);
                *(__nv_bfloat162*)(sPl + r * AK_LD + cq + j) =
                    __nv_bfloat162(__float2bfloat16(p0 - __bfloat162float(h0)),
                                   __float2bfloat16(p1 - __bfloat162float(h1)));
            }
            ls += __shfl_xor_sync(0xffffffffu, ls, 1);
            ls += __shfl_xor_sync(0xffffffffu, ls, 2);
            lrow = lrow * corr + ls;
            mrow = mnew;
            // rescale this thread's O chunk (same row ownership)
            #pragma unroll
            for (int i = 0; i < 4; i++) {
                float4 o = *(float4*)(sO + r * AS_LD + cq + i * 4);
                o.x *= corr; o.y *= corr; o.z *= corr; o.w *= corr;
                *(float4*)(sO + r * AS_LD + cq + i * 4) = o;
            }
        }
        __syncthreads();

        // --- O += P V (bf16x3) ------------------------------------------------
        {
            wmma::fragment<wmma::accumulator, 16, 16, 16, float> oacc[2];
            #pragma unroll
            for (int t = 0; t < 2; t++)
                wmma::load_matrix_sync(oacc[t], sO + (sr * 16) * AS_LD + scw * 32 + t * 16,
                                       AS_LD, wmma::mem_row_major);
            #pragma unroll
            for (int ks = 0; ks < 4; ks++) {
                wmma::fragment<wmma::matrix_a, 16, 16, 16, __nv_bfloat16, wmma::row_major> ph, pl;
                wmma::load_matrix_sync(ph, sPh + (sr * 16) * AK_LD + ks * 16, AK_LD);
                wmma::load_matrix_sync(pl, sPl + (sr * 16) * AK_LD + ks * 16, AK_LD);
                #pragma unroll
                for (int t = 0; t < 2; t++) {
                    wmma::fragment<wmma::matrix_b, 16, 16, 16, __nv_bfloat16, wmma::row_major> vh_, vl_;
                    const int nb = scw * 32 + t * 16;
                    wmma::load_matrix_sync(vh_, sVh + (ks * 16) * AK_LD + nb, AK_LD);
                    wmma::load_matrix_sync(vl_, sVl + (ks * 16) * AK_LD + nb, AK_LD);
                    wmma::mma_sync(oacc[t], ph, vh_, oacc[t]);
                    wmma::mma_sync(oacc[t], ph, vl_, oacc[t]);
                    wmma::mma_sync(oacc[t], pl, vh_, oacc[t]);
                }
            }
            #pragma unroll
            for (int t = 0; t < 2; t++)
                wmma::store_matrix_sync(sO + (sr * 16) * AS_LD + scw * 32 + t * 16,
                                        oacc[t], AS_LD, wmma::mem_row_major);
        }
    }
    __syncthreads();

    // --- finalize: O /= l, split hi/lo, write Y[b, q0+r, h*64+d] ---------------
    {
        const float inv_l = 1.0f / lrow;
        const size_t yoff = ((size_t)b * Tc + q0 + r) * Cc + h * HDc + cq;
        #pragma unroll
        for (int i = 0; i < 4; i++) {
            float4 o = *(const float4*)(sO + r * AS_LD + cq + i * 4);
            float f0 = o.x * inv_l, f1 = o.y * inv_l, f2 = o.z * inv_l, f3 = o.w * inv_l;
            __nv_bfloat16 h0 = __float2bfloat16(f0), h1 = __float2bfloat16(f1);
            __nv_bfloat16 h2 = __float2bfloat16(f2), h3 = __float2bfloat16(f3);
            __nv_bfloat162* hp = (__nv_bfloat162*)(Yhi + yoff + i * 4);
            __nv_bfloat162* lp = (__nv_bfloat162*)(Ylo + yoff + i * 4);
            hp[0] = __nv_bfloat162(h0, h1);
            hp[1] = __nv_bfloat162(h2, h3);
            lp[0] = __nv_bfloat162(__float2bfloat16(f0 - __bfloat162float(h0)),
                                   __float2bfloat16(f1 - __bfloat162float(h1)));
            lp[1] = __nv_bfloat162(__float2bfloat16(f2 - __bfloat162float(h2)),
                                   __float2bfloat16(f3 - __bfloat162float(h3)));
        }
    }
}

// ---------------------------------------------------------------------------
extern "C" void kernel_launch(void* const* d_in, const int* in_sizes, int n_in,
                              void* d_out, int out_size)
{
    const float* x  = (const float*)d_in[0];
    const float* Wq = (const float*)d_in[1];
    const float* Wk = (const float*)d_in[2];
    const float* Wv = (const float*)d_in[3];
    const float* Wo = (const float*)d_in[4];
    float* out = (float*)d_out;

    __nv_bfloat16 *qhi, *qlo, *khi, *klo, *vhi, *vlo;
    __nv_bfloat16 *xhi, *xlo, *yhi, *ylo, *whi, *wlo;
    cudaGetSymbolAddress((void**)&qhi, g_qhi);
    cudaGetSymbolAddress((void**)&qlo, g_qlo);
    cudaGetSymbolAddress((void**)&khi, g_khi);
    cudaGetSymbolAddress((void**)&klo, g_klo);
    cudaGetSymbolAddress((void**)&vhi, g_vhi);
    cudaGetSymbolAddress((void**)&vlo, g_vlo);
    cudaGetSymbolAddress((void**)&xhi, g_xhi);
    cudaGetSymbolAddress((void**)&xlo, g_xlo);
    cudaGetSymbolAddress((void**)&yhi, g_yhi);
    cudaGetSymbolAddress((void**)&ylo, g_ylo);
    cudaGetSymbolAddress((void**)&whi, g_whi);
    cudaGetSymbolAddress((void**)&wlo, g_wlo);

    const int M = Bc * Tc;       // 4096
    const int NELX = M * Cc;     // 4 M
    const int NELW = Cc * Cc;    // 1 M

    split_kernel<<<(NELX / 4 + 255) / 256, 256>>>(x, xhi, xlo, NELX / 4);
    split_kernel<<<(NELW / 4 + 255) / 256, 256>>>(Wq, whi + 0 * NELW, wlo + 0 * NELW, NELW / 4);
    split_kernel<<<(NELW / 4 + 255) / 256, 256>>>(Wk, whi + 1 * NELW, wlo + 1 * NELW, NELW / 4);
    split_kernel<<<(NELW / 4 + 255) / 256, 256>>>(Wv, whi + 2 * NELW, wlo + 2 * NELW, NELW / 4);
    split_kernel<<<(NELW / 4 + 255) / 256, 256>>>(Wo, whi + 3 * NELW, wlo + 3 * NELW, NELW / 4);

    const dim3 ggrid(Cc / BN, M / BM);  // (8, 32)

    cudaFuncSetAttribute(gemm_bf16x3_kernel<0>,
                         cudaFuncAttributeMaxDynamicSharedMemorySize, GSMEM_BYTES);
    cudaFuncSetAttribute(gemm_bf16x3_kernel<1>,
                         cudaFuncAttributeMaxDynamicSharedMemorySize, GSMEM_BYTES);

    // Q gets the exact pow2 softmax scale folded in (1/sqrt(64) = 0.125)
    gemm_bf16x3_kernel<1><<<ggrid, 256, GSMEM_BYTES>>>(
        xhi, xlo, whi + 0 * NELW, wlo + 0 * NELW, nullptr, qhi, qlo, 0.125f, M, Cc, Cc);
    gemm_bf16x3_kernel<1><<<ggrid, 256, GSMEM_BYTES>>>(
        xhi, xlo, whi + 1 * NELW, wlo + 1 * NELW, nullptr, khi, klo, 1.0f, M, Cc, Cc);
    gemm_bf16x3_kernel<1><<<ggrid, 256, GSMEM_BYTES>>>(
        xhi, xlo, whi + 2 * NELW, wlo + 2 * NELW, nullptr, vhi, vlo, 1.0f, M, Cc, Cc);

    cudaFuncSetAttribute(attn_tc_kernel,
                         cudaFuncAttributeMaxDynamicSharedMemorySize, ASMEM_BYTES);
    attn_tc_kernel<<<dim3(Tc / 64, NHc, Bc), 256, ASMEM_BYTES>>>(
        qhi, qlo, khi, klo, vhi, vlo, yhi, ylo);

    gemm_bf16x3_kernel<0><<<ggrid, 256, GSMEM_BYTES>>>(
        yhi, ylo, whi + 3 * NELW, wlo + 3 * NELW, out, nullptr, nullptr, 1.0f, M, Cc, Cc);
}

// round 7
// speedup vs baseline: 2.6361x; 1.3937x over previous
#include <cuda_runtime.h>
#include <cuda_bf16.h>
#include <mma.h>
#include <math.h>
#include <stdint.h>

using namespace nvcuda;

#define Bc  2
#define Tc  2048
#define Cc  1024
#define NHc 16
#define HDc 64

// Q scale: 1/sqrt(64) * log2(e)  (softmax done in exp2 domain)
#define QSCALE 0.18033688011112042f

// ---------------- scratch (device globals; no allocation allowed) ----------
__device__ __nv_bfloat16 g_qhi[Bc * NHc * Tc * HDc];
__device__ __nv_bfloat16 g_qlo[Bc * NHc * Tc * HDc];
__device__ __nv_bfloat16 g_khi[Bc * NHc * Tc * HDc];
__device__ __nv_bfloat16 g_klo[Bc * NHc * Tc * HDc];
__device__ __nv_bfloat16 g_vhi[Bc * NHc * Tc * HDc];
__device__ __nv_bfloat16 g_vlo[Bc * NHc * Tc * HDc];
__device__ __nv_bfloat16 g_xhi[Bc * Tc * Cc];
__device__ __nv_bfloat16 g_xlo[Bc * Tc * Cc];
__device__ __nv_bfloat16 g_yhi[Bc * Tc * Cc];
__device__ __nv_bfloat16 g_ylo[Bc * Tc * Cc];
__device__ __nv_bfloat16 g_whi[4][Cc * Cc];
__device__ __nv_bfloat16 g_wlo[4][Cc * Cc];

// ---------------- fp32 -> bf16 hi/lo split (4 elems/thread) -----------------
__global__ __launch_bounds__(256) void split_kernel(
    const float* __restrict__ x, __nv_bfloat16* __restrict__ hi,
    __nv_bfloat16* __restrict__ lo, int n4)
{
    int i = blockIdx.x * 256 + threadIdx.x;
    if (i < n4) {
        float4 v = ((const float4*)x)[i];
        __nv_bfloat16 h0 = __float2bfloat16(v.x), h1 = __float2bfloat16(v.y);
        __nv_bfloat16 h2 = __float2bfloat16(v.z), h3 = __float2bfloat16(v.w);
        __nv_bfloat162* hp = (__nv_bfloat162*)(hi + i * 4);
        __nv_bfloat162* lp = (__nv_bfloat162*)(lo + i * 4);
        hp[0] = __nv_bfloat162(h0, h1);
        hp[1] = __nv_bfloat162(h2, h3);
        lp[0] = __nv_bfloat162(__float2bfloat16(v.x - __bfloat162float(h0)),
                               __float2bfloat16(v.y - __bfloat162float(h1)));
        lp[1] = __nv_bfloat162(__float2bfloat16(v.z - __bfloat162float(h2)),
                               __float2bfloat16(v.w - __bfloat162float(h3)));
    }
}

// ---------------- async-copy / mma helpers -----------------------------------
__device__ __forceinline__ void cp_async16_s(uint32_t saddr, const void* g) {
    asm volatile("cp.async.cg.shared.global [%0], [%1], 16;\n" :: "r"(saddr), "l"(g));
}
__device__ __forceinline__ void cp_async_16(void* smem, const void* gmem) {
    unsigned s = (unsigned)__cvta_generic_to_shared(smem);
    asm volatile("cp.async.cg.shared.global [%0], [%1], 16;\n" :: "r"(s), "l"(gmem));
}
__device__ __forceinline__ void cp_commit() {
    asm volatile("cp.async.commit_group;\n");
}
template <int N>
__device__ __forceinline__ void cp_wait() {
    asm volatile("cp.async.wait_group %0;\n" :: "n"(N));
}

__device__ __forceinline__ void ldsm4(uint32_t* r, uint32_t a) {
    asm volatile("ldmatrix.sync.aligned.m8n8.x4.shared.b16 {%0,%1,%2,%3}, [%4];"
                 : "=r"(r[0]), "=r"(r[1]), "=r"(r[2]), "=r"(r[3]) : "r"(a));
}
__device__ __forceinline__ void ldsm4t(uint32_t* r, uint32_t a) {
    asm volatile("ldmatrix.sync.aligned.m8n8.x4.trans.shared.b16 {%0,%1,%2,%3}, [%4];"
                 : "=r"(r[0]), "=r"(r[1]), "=r"(r[2]), "=r"(r[3]) : "r"(a));
}
__device__ __forceinline__ void mma_bf16(float* d, const uint32_t* a,
                                         uint32_t b0, uint32_t b1) {
    asm volatile(
        "mma.sync.aligned.m16n8k16.row.col.f32.bf16.bf16.f32 "
        "{%0,%1,%2,%3}, {%4,%5,%6,%7}, {%8,%9}, {%0,%1,%2,%3};"
        : "+f"(d[0]), "+f"(d[1]), "+f"(d[2]), "+f"(d[3])
        : "r"(a[0]), "r"(a[1]), "r"(a[2]), "r"(a[3]), "r"(b0), "r"(b1));
}
__device__ __forceinline__ uint32_t pack_bf16(float a, float b) {
    __nv_bfloat162 h = __floats2bfloat162_rn(a, b);
    return *(uint32_t*)&h;
}

// ---------------------------------------------------------------------------
// bf16x3 NT GEMM (wmma):  O = A @ W^T
// MODE 0: fp32 direct store [M, Ntot].
// MODE 1: fused QKV epilogue (Ntot=3072): per-slab scale + hi/lo split +
//         scatter to [b,h,t,d].
// CTA tile 128x128, BK=16, 8 warps, 4-stage cp.async.
// ---------------------------------------------------------------------------
#define BM 128
#define BN 128
#define BK 16
#define STAGES 4
#define LDMH 24
#define MAT_HALVES (128 * LDMH)
#define STAGE_HALVES (4 * MAT_HALVES)
#define GSMEM_BYTES (STAGES * STAGE_HALVES * 2)  // 98304

template <int MODE>
__global__ __launch_bounds__(256) void gemm_bf16x3_kernel(
    const __nv_bfloat16* __restrict__ Ahi, const __nv_bfloat16* __restrict__ Alo,
    const __nv_bfloat16* __restrict__ Whi, const __nv_bfloat16* __restrict__ Wlo,
    float* __restrict__ O, int Ntot,
    __nv_bfloat16* __restrict__ Qhi, __nv_bfloat16* __restrict__ Qlo,
    __nv_bfloat16* __restrict__ Khi, __nv_bfloat16* __restrict__ Klo,
    __nv_bfloat16* __restrict__ Vhi, __nv_bfloat16* __restrict__ Vlo)
{
    extern __shared__ __align__(16) __nv_bfloat16 sm[];
    const int K = Cc;

    const int tid = threadIdx.x;
    const int m0 = blockIdx.y * BM;
    const int n0 = blockIdx.x * BN;

    const int wid = tid >> 5;
    const int wm = wid & 3;
    const int wn = wid >> 2;

    const int lrow = tid >> 1;
    const int lh8 = (tid & 1) * 8;

    const __nv_bfloat16* gAhi = Ahi + (size_t)(m0 + lrow) * K + lh8;
    const __nv_bfloat16* gAlo = Alo + (size_t)(m0 + lrow) * K + lh8;
    const __nv_bfloat16* gWhi = Whi + (size_t)(n0 + lrow) * K + lh8;
    const __nv_bfloat16* gWlo = Wlo + (size_t)(n0 + lrow) * K + lh8;
    __nv_bfloat16* sdst = sm + lrow * LDMH + lh8;

    const int nchunks = K / BK;

    auto load_stage = [&](int stage, int chunk) {
        __nv_bfloat16* base = sdst + stage * STAGE_HALVES;
        const int koff = chunk * BK;
        cp_async_16(base + 0 * MAT_HALVES, gAhi + koff);
        cp_async_16(base + 1 * MAT_HALVES, gAlo + koff);
        cp_async_16(base + 2 * MAT_HALVES, gWhi + koff);
        cp_async_16(base + 3 * MAT_HALVES, gWlo + koff);
        cp_commit();
    };

    #pragma unroll
    for (int s = 0; s < STAGES - 1; s++) load_stage(s, s);

    wmma::fragment<wmma::accumulator, 16, 16, 16, float> acc[2][4];
    #pragma unroll
    for (int i = 0; i < 2; i++)
        #pragma unroll
        for (int j = 0; j < 4; j++) wmma::fill_fragment(acc[i][j], 0.0f);

    for (int chunk = 0; chunk < nchunks; chunk++) {
        cp_wait<STAGES - 2>();
        __syncthreads();

        if (chunk + STAGES - 1 < nchunks)
            load_stage((chunk + STAGES - 1) % STAGES, chunk + STAGES - 1);

        const __nv_bfloat16* st = sm + (chunk % STAGES) * STAGE_HALVES;
        const __nv_bfloat16* sAhi = st + 0 * MAT_HALVES;
        const __nv_bfloat16* sAlo = st + 1 * MAT_HALVES;
        const __nv_bfloat16* sWhi = st + 2 * MAT_HALVES;
        const __nv_bfloat16* sWlo = st + 3 * MAT_HALVES;

        wmma::fragment<wmma::matrix_a, 16, 16, 16, __nv_bfloat16, wmma::row_major> ah[2], al[2];
        wmma::fragment<wmma::matrix_b, 16, 16, 16, __nv_bfloat16, wmma::col_major> bh[4], bl[4];

        #pragma unroll
        for (int i = 0; i < 2; i++) {
            wmma::load_matrix_sync(ah[i], sAhi + (wm * 32 + i * 16) * LDMH, LDMH);
            wmma::load_matrix_sync(al[i], sAlo + (wm * 32 + i * 16) * LDMH, LDMH);
        }
        #pragma unroll
        for (int j = 0; j < 4; j++) {
            wmma::load_matrix_sync(bh[j], sWhi + (wn * 64 + j * 16) * LDMH, LDMH);
            wmma::load_matrix_sync(bl[j], sWlo + (wn * 64 + j * 16) * LDMH, LDMH);
        }

        #pragma unroll
        for (int i = 0; i < 2; i++)
            #pragma unroll
            for (int j = 0; j < 4; j++) {
                wmma::mma_sync(acc[i][j], ah[i], bh[j], acc[i][j]);
                wmma::mma_sync(acc[i][j], ah[i], bl[j], acc[i][j]);
                wmma::mma_sync(acc[i][j], al[i], bh[j], acc[i][j]);
            }
        __syncthreads();
    }

    if (MODE == 0) {
        #pragma unroll
        for (int i = 0; i < 2; i++) {
            const int m = m0 + wm * 32 + i * 16;
            #pragma unroll
            for (int j = 0; j < 4; j++) {
                const int n = n0 + wn * 64 + j * 16;
                wmma::store_matrix_sync(O + (size_t)m * Ntot + n, acc[i][j], Ntot,
                                        wmma::mem_row_major);
            }
        }
    } else {
        __syncthreads();
        float* sf = (float*)sm;  // 128 x 132
        #pragma unroll
        for (int i = 0; i < 2; i++)
            #pragma unroll
            for (int j = 0; j < 4; j++)
                wmma::store_matrix_sync(sf + (wm * 32 + i * 16) * 132 + wn * 64 + j * 16,
                                        acc[i][j], 132, wmma::mem_row_major);
        __syncthreads();

        #pragma unroll
        for (int it = 0; it < 16; it++) {
            const int idx = tid + it * 256;
            const int r = idx >> 5;
            const int c4 = (idx & 31) << 2;
            float4 v = *(const float4*)(sf + r * 132 + c4);
            const int m = m0 + r, n = n0 + c4;
            const int mat = n >> 10;           // 0=Q,1=K,2=V
            const int within = n & 1023;
            const int hh = within >> 6, dd = within & 63;
            const float sc = (mat == 0) ? QSCALE : 1.0f;
            __nv_bfloat16* hi = (mat == 0) ? Qhi : (mat == 1) ? Khi : Vhi;
            __nv_bfloat16* lo = (mat == 0) ? Qlo : (mat == 1) ? Klo : Vlo;
            const int b = m >> 11, tt = m & 2047;
            const size_t off = (((size_t)(b * NHc + hh)) * Tc + tt) * HDc + dd;
            float f0 = v.x * sc, f1 = v.y * sc, f2 = v.z * sc, f3 = v.w * sc;
            __nv_bfloat16 h0 = __float2bfloat16(f0), h1 = __float2bfloat16(f1);
            __nv_bfloat16 h2 = __float2bfloat16(f2), h3 = __float2bfloat16(f3);
            __nv_bfloat162* hp = (__nv_bfloat162*)(hi + off);
            __nv_bfloat162* lp = (__nv_bfloat162*)(lo + off);
            hp[0] = __nv_bfloat162(h0, h1);
            hp[1] = __nv_bfloat162(h2, h3);
            lp[0] = __nv_bfloat162(__float2bfloat16(f0 - __bfloat162float(h0)),
                                   __float2bfloat16(f1 - __bfloat162float(h1)));
            lp[1] = __nv_bfloat162(__float2bfloat16(f2 - __bfloat162float(h2)),
                                   __float2bfloat16(f3 - __bfloat162float(h3)));
        }
    }
}

// ---------------------------------------------------------------------------
// Register-resident FA2 causal attention (bf16x3, fp32 softmax/accum).
// CTA: 128 q rows, 8 warps x 16 rows. kv tiles of 64, double-buffered cp.async.
// Q pre-scaled by 0.125*log2(e); softmax in exp2 domain.
// ---------------------------------------------------------------------------
#define ALD 72                    // halves per smem row (144B, ldsm conflict-free)
#define ATB (64 * ALD * 2)        // 9216 bytes per 64x64 tile
#define ASMEM_BYTES (8 * ATB)     // 73728: 2 stages x {KH,KL,VH,VL}

__global__ __launch_bounds__(256, 1) void attn_fa2_kernel(
    const __nv_bfloat16* __restrict__ Qhi, const __nv_bfloat16* __restrict__ Qlo,
    const __nv_bfloat16* __restrict__ Khi_g, const __nv_bfloat16* __restrict__ Klo_g,
    const __nv_bfloat16* __restrict__ Vhi_g, const __nv_bfloat16* __restrict__ Vlo_g,
    __nv_bfloat16* __restrict__ Yhi, __nv_bfloat16* __restrict__ Ylo)
{
    extern __shared__ __align__(16) char asm_[];
    const uint32_t sbase = (uint32_t)__cvta_generic_to_shared(asm_);

    const int tid = threadIdx.x;
    const int w = tid >> 5;
    const int lane = tid & 31;
    const int g = lane >> 2;       // acc row within 8
    const int t = lane & 3;        // acc col group

    const int qt = (int)gridDim.x - 1 - (int)blockIdx.x;  // heavy tiles first
    const int h = blockIdx.y, b = blockIdx.z;
    const int q0 = qt * 128;

    const size_t bh = (size_t)(b * NHc + h) * Tc;
    const __nv_bfloat16* qhp = Qhi + (bh + q0) * HDc;
    const __nv_bfloat16* qlp = Qlo + (bh + q0) * HDc;
    const __nv_bfloat16* khp = Khi_g + bh * HDc;
    const __nv_bfloat16* klp = Klo_g + bh * HDc;
    const __nv_bfloat16* vhp = Vhi_g + bh * HDc;
    const __nv_bfloat16* vlp = Vlo_g + bh * HDc;

    auto buf = [&](int stg, int mat) -> uint32_t {
        return sbase + (uint32_t)(stg * 4 + mat) * ATB;
    };

    auto load_kv = [&](int kt, int stg) {
        const int k0 = kt * 64;
        #pragma unroll
        for (int s = 0; s < 8; s++) {
            const int idx = s * 256 + tid;
            const int mat = s >> 1;          // 512 segs per matrix
            const int within = idx & 511;
            const int row = within >> 3;
            const int seg = within & 7;
            const __nv_bfloat16* src =
                (mat == 0 ? khp : mat == 1 ? klp : mat == 2 ? vhp : vlp) +
                (size_t)(k0 + row) * HDc + seg * 8;
            cp_async16_s(buf(stg, mat) + (uint32_t)(row * ALD + seg * 8) * 2, src);
        }
        cp_commit();
    };

    // ---- stage Q (128x64 hi/lo) into stage-1 buffers ------------------------
    {
        #pragma unroll
        for (int s = 0; s < 8; s++) {
            const int idx = s * 256 + tid;
            const int matq = s >> 2;          // 0=hi,1=lo (1024 segs each)
            const int within = idx & 1023;
            const int row = within >> 3;
            const int seg = within & 7;
            const __nv_bfloat16* src = (matq ? qlp : qhp) + (size_t)row * HDc + seg * 8;
            const int dstmat = matq * 2 + (row >> 6);  // hi->{0,1}, lo->{2,3}
            cp_async16_s(buf(1, dstmat) + (uint32_t)((row & 63) * ALD + seg * 8) * 2, src);
        }
        cp_commit();
    }
    load_kv(0, 0);
    cp_wait<1>();      // Q staged (kv tile0 may still be in flight)
    __syncthreads();

    // ---- persistent Q fragments ---------------------------------------------
    uint32_t qh[4][4], ql[4][4];
    {
        const int qrow = w * 16;
        const uint32_t hb = buf(1, qrow < 64 ? 0 : 1);
        const uint32_t lb = buf(1, qrow < 64 ? 2 : 3);
        const int r0 = qrow & 63;
        const int arow = (lane & 7) + ((lane >> 3) & 1) * 8;
        const int acol = (lane >> 4) * 8;
        #pragma unroll
        for (int ks = 0; ks < 4; ks++) {
            ldsm4(qh[ks], hb + (uint32_t)((r0 + arow) * ALD + ks * 16 + acol) * 2);
            ldsm4(ql[ks], lb + (uint32_t)((r0 + arow) * ALD + ks * 16 + acol) * 2);
        }
    }

    float oacc[8][4];
    #pragma unroll
    for (int j = 0; j < 8; j++)
        #pragma unroll
        for (int e = 0; e < 4; e++) oacc[j][e] = 0.0f;
    float m0 = -1e30f, m1 = -1e30f, l0 = 0.0f, l1 = 0.0f;

    const int qrow0 = q0 + w * 16 + g;
    const int qrow1 = qrow0 + 8;
    const int nkt = 2 * qt + 2;

    // lane address offsets
    const int b_nrow = (lane & 7) + (lane >> 4) * 8;        // K: n row
    const int b_kcol = ((lane >> 3) & 1) * 8;               // K: k col
    const int v_krow = (lane & 7) + ((lane >> 3) & 1) * 8;  // V: k row
    const int v_ncol = (lane >> 4) * 8;                     // V: n col

    for (int kt = 0; kt < nkt; kt++) {
        cp_wait<0>();
        __syncthreads();
        if (kt + 1 < nkt) load_kv(kt + 1, (kt + 1) & 1);
        const int stg = kt & 1;
        const uint32_t kh_b = buf(stg, 0), kl_b = buf(stg, 1);
        const uint32_t vh_b = buf(stg, 2), vl_b = buf(stg, 3);

        // ---- S = Q K^T -------------------------------------------------------
        float sacc[8][4];
        #pragma unroll
        for (int j = 0; j < 8; j++)
            #pragma unroll
            for (int e = 0; e < 4; e++) sacc[j][e] = 0.0f;

        #pragma unroll
        for (int ks = 0; ks < 4; ks++) {
            #pragma unroll
            for (int p = 0; p < 4; p++) {
                const uint32_t off =
                    (uint32_t)((p * 16 + b_nrow) * ALD + ks * 16 + b_kcol) * 2;
                uint32_t kh4[4], kl4[4];
                ldsm4(kh4, kh_b + off);
                ldsm4(kl4, kl_b + off);
                mma_bf16(sacc[2 * p + 0], qh[ks], kh4[0], kh4[1]);
                mma_bf16(sacc[2 * p + 0], qh[ks], kl4[0], kl4[1]);
                mma_bf16(sacc[2 * p + 0], ql[ks], kh4[0], kh4[1]);
                mma_bf16(sacc[2 * p + 1], qh[ks], kh4[2], kh4[3]);
                mma_bf16(sacc[2 * p + 1], qh[ks], kl4[2], kl4[3]);
                mma_bf16(sacc[2 * p + 1], ql[ks], kh4[2], kh4[3]);
            }
        }

        // ---- mask + online softmax (registers) --------------------------------
        if (kt >= 2 * qt) {
            #pragma unroll
            for (int j = 0; j < 8; j++) {
                const int kc = kt * 64 + j * 8 + t * 2;
                if (kc     > qrow0) sacc[j][0] = -1e30f;
                if (kc + 1 > qrow0) sacc[j][1] = -1e30f;
                if (kc     > qrow1) sacc[j][2] = -1e30f;
                if (kc + 1 > qrow1) sacc[j][3] = -1e30f;
            }
        }
        float mx0 = -1e30f, mx1 = -1e30f;
        #pragma unroll
        for (int j = 0; j < 8; j++) {
            mx0 = fmaxf(mx0, fmaxf(sacc[j][0], sacc[j][1]));
            mx1 = fmaxf(mx1, fmaxf(sacc[j][2], sacc[j][3]));
        }
        mx0 = fmaxf(mx0, __shfl_xor_sync(0xffffffffu, mx0, 1));
        mx0 = fmaxf(mx0, __shfl_xor_sync(0xffffffffu, mx0, 2));
        mx1 = fmaxf(mx1, __shfl_xor_sync(0xffffffffu, mx1, 1));
        mx1 = fmaxf(mx1, __shfl_xor_sync(0xffffffffu, mx1, 2));

        const float mn0 = fmaxf(m0, mx0), mn1 = fmaxf(m1, mx1);
        const float c0 = exp2f(m0 - mn0), c1 = exp2f(m1 - mn1);
        m0 = mn0; m1 = mn1;

        uint32_t pah[8][2], pal[8][2];
        float s0 = 0.0f, s1 = 0.0f;
        #pragma unroll
        for (int j = 0; j < 8; j++) {
            const float p0 = exp2f(sacc[j][0] - mn0);
            const float p1 = exp2f(sacc[j][1] - mn0);
            const float p2 = exp2f(sacc[j][2] - mn1);
            const float p3 = exp2f(sacc[j][3] - mn1);
            s0 += p0 + p1; s1 += p2 + p3;
            const float h0 = __bfloat162float(__float2bfloat16(p0));
            const float h1 = __bfloat162float(__float2bfloat16(p1));
            const float h2 = __bfloat162float(__float2bfloat16(p2));
            const float h3 = __bfloat162float(__float2bfloat16(p3));
            pah[j][0] = pack_bf16(h0, h1);
            pah[j][1] = pack_bf16(h2, h3);
            pal[j][0] = pack_bf16(p0 - h0, p1 - h1);
            pal[j][1] = pack_bf16(p2 - h2, p3 - h3);
        }
        l0 = l0 * c0 + s0;
        l1 = l1 * c1 + s1;
        #pragma unroll
        for (int j = 0; j < 8; j++) {
            oacc[j][0] *= c0; oacc[j][1] *= c0;
            oacc[j][2] *= c1; oacc[j][3] *= c1;
        }

        // ---- O += P V ----------------------------------------------------------
        #pragma unroll
        for (int ks = 0; ks < 4; ks++) {
            uint32_t afh[4] = {pah[2 * ks][0], pah[2 * ks][1],
                               pah[2 * ks + 1][0], pah[2 * ks + 1][1]};
            uint32_t afl[4] = {pal[2 * ks][0], pal[2 * ks][1],
                               pal[2 * ks + 1][0], pal[2 * ks + 1][1]};
            #pragma unroll
            for (int p = 0; p < 4; p++) {
                const uint32_t off =
                    (uint32_t)((ks * 16 + v_krow) * ALD + p * 16 + v_ncol) * 2;
                uint32_t vh4[4], vl4[4];
                ldsm4t(vh4, vh_b + off);
                ldsm4t(vl4, vl_b + off);
                mma_bf16(oacc[2 * p + 0], afh, vh4[0], vh4[1]);
                mma_bf16(oacc[2 * p + 0], afh, vl4[0], vl4[1]);
                mma_bf16(oacc[2 * p + 0], afl, vh4[0], vh4[1]);
                mma_bf16(oacc[2 * p + 1], afh, vh4[2], vh4[3]);
                mma_bf16(oacc[2 * p + 1], afh, vl4[2], vl4[3]);
                mma_bf16(oacc[2 * p + 1], afl, vh4[2], vh4[3]);
            }
        }
    }

    // ---- finalize: l reduce, normalize, hi/lo split, store --------------------
    l0 += __shfl_xor_sync(0xffffffffu, l0, 1);
    l0 += __shfl_xor_sync(0xffffffffu, l0, 2);
    l1 += __shfl_xor_sync(0xffffffffu, l1, 1);
    l1 += __shfl_xor_sync(0xffffffffu, l1, 2);
    const float i0 = 1.0f / l0, i1 = 1.0f / l1;

    const size_t y0 = ((size_t)b * Tc + qrow0) * Cc + h * HDc + t * 2;
    const size_t y1 = ((size_t)b * Tc + qrow1) * Cc + h * HDc + t * 2;
    #pragma unroll
    for (int j = 0; j < 8; j++) {
        const float f0 = oacc[j][0] * i0, f1 = oacc[j][1] * i0;
        const float f2 = oacc[j][2] * i1, f3 = oacc[j][3] * i1;
        const float h0 = __bfloat162float(__float2bfloat16(f0));
        const float h1 = __bfloat162float(__float2bfloat16(f1));
        const float h2 = __bfloat162float(__float2bfloat16(f2));
        const float h3 = __bfloat162float(__float2bfloat16(f3));
        *(uint32_t*)(Yhi + y0 + j * 8) = pack_bf16(h0, h1);
        *(uint32_t*)(Ylo + y0 + j * 8) = pack_bf16(f0 - h0, f1 - h1);
        *(uint32_t*)(Yhi + y1 + j * 8) = pack_bf16(h2, h3);
        *(uint32_t*)(Ylo + y1 + j * 8) = pack_bf16(f2 - h2, f3 - h3);
    }
}

// ---------------------------------------------------------------------------
extern "C" void kernel_launch(void* const* d_in, const int* in_sizes, int n_in,
                              void* d_out, int out_size)
{
    const float* x  = (const float*)d_in[0];
    const float* Wq = (const float*)d_in[1];
    const float* Wk = (const float*)d_in[2];
    const float* Wv = (const float*)d_in[3];
    const float* Wo = (const float*)d_in[4];
    float* out = (float*)d_out;

    __nv_bfloat16 *qhi, *qlo, *khi, *klo, *vhi, *vlo;
    __nv_bfloat16 *xhi, *xlo, *yhi, *ylo, *whi, *wlo;
    cudaGetSymbolAddress((void**)&qhi, g_qhi);
    cudaGetSymbolAddress((void**)&qlo, g_qlo);
    cudaGetSymbolAddress((void**)&khi, g_khi);
    cudaGetSymbolAddress((void**)&klo, g_klo);
    cudaGetSymbolAddress((void**)&vhi, g_vhi);
    cudaGetSymbolAddress((void**)&vlo, g_vlo);
    cudaGetSymbolAddress((void**)&xhi, g_xhi);
    cudaGetSymbolAddress((void**)&xlo, g_xlo);
    cudaGetSymbolAddress((void**)&yhi, g_yhi);
    cudaGetSymbolAddress((void**)&ylo, g_ylo);
    cudaGetSymbolAddress((void**)&whi, g_whi);
    cudaGetSymbolAddress((void**)&wlo, g_wlo);

    const int M = Bc * Tc;       // 4096
    const int NELX = M * Cc;     // 4 M
    const int NELW = Cc * Cc;    // 1 M

    split_kernel<<<(NELX / 4 + 255) / 256, 256>>>(x, xhi, xlo, NELX / 4);
    split_kernel<<<(NELW / 4 + 255) / 256, 256>>>(Wq, whi + 0 * NELW, wlo + 0 * NELW, NELW / 4);
    split_kernel<<<(NELW / 4 + 255) / 256, 256>>>(Wk, whi + 1 * NELW, wlo + 1 * NELW, NELW / 4);
    split_kernel<<<(NELW / 4 + 255) / 256, 256>>>(Wv, whi + 2 * NELW, wlo + 2 * NELW, NELW / 4);
    split_kernel<<<(NELW / 4 + 255) / 256, 256>>>(Wo, whi + 3 * NELW, wlo + 3 * NELW, NELW / 4);

    cudaFuncSetAttribute(gemm_bf16x3_kernel<0>,
                         cudaFuncAttributeMaxDynamicSharedMemorySize, GSMEM_BYTES);
    cudaFuncSetAttribute(gemm_bf16x3_kernel<1>,
                         cudaFuncAttributeMaxDynamicSharedMemorySize, GSMEM_BYTES);

    // Fused QKV projection: N = 3072 (Wq|Wk|Wv concatenated in g_whi/g_wlo)
    gemm_bf16x3_kernel<1><<<dim3(3 * Cc / BN, M / BM), 256, GSMEM_BYTES>>>(
        xhi, xlo, whi, wlo, nullptr, 3 * Cc,
        qhi, qlo, khi, klo, vhi, vlo);

    cudaFuncSetAttribute(attn_fa2_kernel,
                         cudaFuncAttributeMaxDynamicSharedMemorySize, ASMEM_BYTES);
    attn_fa2_kernel<<<dim3(Tc / 128, NHc, Bc), 256, ASMEM_BYTES>>>(
        qhi, qlo, khi, klo, vhi, vlo, yhi, ylo);

    // Output projection: fp32 direct
    gemm_bf16x3_kernel<0><<<dim3(Cc / BN, M / BM), 256, GSMEM_BYTES>>>(
        yhi, ylo, whi + 3 * NELW, wlo + 3 * NELW, out, Cc,
        nullptr, nullptr, nullptr, nullptr, nullptr, nullptr);
}

// round 8
// speedup vs baseline: 2.8329x; 1.0746x over previous
#include <cuda_runtime.h>
#include <cuda_bf16.h>
#include <math.h>
#include <stdint.h>

#define Bc  2
#define Tc  2048
#define Cc  1024
#define NHc 16
#define HDc 64

// Q scale: 1/sqrt(64) * log2(e)  (softmax done in exp2 domain)
#define QSCALE 0.18033688011112042f

// ---------------- scratch (device globals; no allocation allowed) ----------
__device__ __nv_bfloat16 g_qhi[Bc * NHc * Tc * HDc];
__device__ __nv_bfloat16 g_qlo[Bc * NHc * Tc * HDc];
__device__ __nv_bfloat16 g_khi[Bc * NHc * Tc * HDc];
__device__ __nv_bfloat16 g_klo[Bc * NHc * Tc * HDc];
__device__ __nv_bfloat16 g_vhi[Bc * NHc * Tc * HDc];
__device__ __nv_bfloat16 g_vlo[Bc * NHc * Tc * HDc];
__device__ __nv_bfloat16 g_xhi[Bc * Tc * Cc];
__device__ __nv_bfloat16 g_xlo[Bc * Tc * Cc];
__device__ __nv_bfloat16 g_yhi[Bc * Tc * Cc];
__device__ __nv_bfloat16 g_ylo[Bc * Tc * Cc];
__device__ __nv_bfloat16 g_whi[4][Cc * Cc];
__device__ __nv_bfloat16 g_wlo[4][Cc * Cc];

// ---------------- fp32 -> bf16 hi/lo splits ---------------------------------
__device__ __forceinline__ void split_store(float vx, float vy, float vz, float vw,
                                            __nv_bfloat16* hi, __nv_bfloat16* lo,
                                            size_t i4)
{
    __nv_bfloat16 h0 = __float2bfloat16(vx), h1 = __float2bfloat16(vy);
    __nv_bfloat16 h2 = __float2bfloat16(vz), h3 = __float2bfloat16(vw);
    __nv_bfloat162* hp = (__nv_bfloat162*)(hi + i4);
    __nv_bfloat162* lp = (__nv_bfloat162*)(lo + i4);
    hp[0] = __nv_bfloat162(h0, h1);
    hp[1] = __nv_bfloat162(h2, h3);
    lp[0] = __nv_bfloat162(__float2bfloat16(vx - __bfloat162float(h0)),
                           __float2bfloat16(vy - __bfloat162float(h1)));
    lp[1] = __nv_bfloat162(__float2bfloat16(vz - __bfloat162float(h2)),
                           __float2bfloat16(vw - __bfloat162float(h3)));
}

__global__ __launch_bounds__(256) void split_kernel(
    const float* __restrict__ x, __nv_bfloat16* __restrict__ hi,
    __nv_bfloat16* __restrict__ lo, int n4)
{
    int i = blockIdx.x * 256 + threadIdx.x;
    if (i < n4) {
        float4 v = ((const float4*)x)[i];
        split_store(v.x, v.y, v.z, v.w, hi, lo, (size_t)i * 4);
    }
}

// all 4 weight matrices in one launch; NELW/4 = 2^18 float4 per matrix
__global__ __launch_bounds__(256) void split4_kernel(
    const float* __restrict__ w0, const float* __restrict__ w1,
    const float* __restrict__ w2, const float* __restrict__ w3,
    __nv_bfloat16* __restrict__ hi, __nv_bfloat16* __restrict__ lo)
{
    int i = blockIdx.x * 256 + threadIdx.x;       // 0 .. 4*2^18-1
    const int which = i >> 18;
    const int off = i & 262143;
    const float* src = (which == 0) ? w0 : (which == 1) ? w1 : (which == 2) ? w2 : w3;
    float4 v = ((const float4*)src)[off];
    split_store(v.x, v.y, v.z, v.w, hi, lo, (size_t)i * 4);
}

// ---------------- async-copy / mma helpers -----------------------------------
__device__ __forceinline__ void cp_async16_s(uint32_t saddr, const void* g) {
    asm volatile("cp.async.cg.shared.global [%0], [%1], 16;\n" :: "r"(saddr), "l"(g));
}
__device__ __forceinline__ void cp_commit() {
    asm volatile("cp.async.commit_group;\n");
}
template <int N>
__device__ __forceinline__ void cp_wait() {
    asm volatile("cp.async.wait_group %0;\n" :: "n"(N));
}
__device__ __forceinline__ void ldsm4(uint32_t* r, uint32_t a) {
    asm volatile("ldmatrix.sync.aligned.m8n8.x4.shared.b16 {%0,%1,%2,%3}, [%4];"
                 : "=r"(r[0]), "=r"(r[1]), "=r"(r[2]), "=r"(r[3]) : "r"(a));
}
__device__ __forceinline__ void ldsm4t(uint32_t* r, uint32_t a) {
    asm volatile("ldmatrix.sync.aligned.m8n8.x4.trans.shared.b16 {%0,%1,%2,%3}, [%4];"
                 : "=r"(r[0]), "=r"(r[1]), "=r"(r[2]), "=r"(r[3]) : "r"(a));
}
__device__ __forceinline__ void mma_bf16(float* d, const uint32_t* a,
                                         uint32_t b0, uint32_t b1) {
    asm volatile(
        "mma.sync.aligned.m16n8k16.row.col.f32.bf16.bf16.f32 "
        "{%0,%1,%2,%3}, {%4,%5,%6,%7}, {%8,%9}, {%0,%1,%2,%3};"
        : "+f"(d[0]), "+f"(d[1]), "+f"(d[2]), "+f"(d[3])
        : "r"(a[0]), "r"(a[1]), "r"(a[2]), "r"(a[3]), "r"(b0), "r"(b1));
}
__device__ __forceinline__ uint32_t pack_bf16(float a, float b) {
    __nv_bfloat162 h = __floats2bfloat162_rn(a, b);
    return *(uint32_t*)&h;
}

// ---------------------------------------------------------------------------
// bf16x3 NT GEMM (raw mma):  O = A @ W^T,  K = 1024.
// CTA 128x128, 8 warps (4m x 2n), warp tile 32x64. BK=32, 3-stage cp.async.
// MODE 0: fp32 direct store [M, Ntot].
// MODE 1: fused QKV epilogue (Ntot=3072): per-slab scale, hi/lo split,
//         scatter to [b,h,t,d] straight from registers.
// ---------------------------------------------------------------------------
#define GLD 40                        // halves per padded smem row (80 B)
#define GTILE_B (128 * GLD * 2)       // 10240 B per matrix tile
#define GSTAGE_B (4 * GTILE_B)        // 40960 B  (Ahi,Alo,Whi,Wlo)
#define GSTAGES 3
#define GSMEM_BYTES (GSTAGES * GSTAGE_B)  // 122880

template <int MODE>
__global__ __launch_bounds__(256, 1) void gemm_mma_kernel(
    const __nv_bfloat16* __restrict__ Ahi, const __nv_bfloat16* __restrict__ Alo,
    const __nv_bfloat16* __restrict__ Whi, const __nv_bfloat16* __restrict__ Wlo,
    float* __restrict__ O, int Ntot,
    __nv_bfloat16* __restrict__ Qhi, __nv_bfloat16* __restrict__ Qlo,
    __nv_bfloat16* __restrict__ Khi, __nv_bfloat16* __restrict__ Klo,
    __nv_bfloat16* __restrict__ Vhi, __nv_bfloat16* __restrict__ Vlo)
{
    extern __shared__ __align__(16) char gsm[];
    const uint32_t sbase = (uint32_t)__cvta_generic_to_shared(gsm);
    const int K = Cc;

    const int tid = threadIdx.x;
    const int wid = tid >> 5;
    const int lane = tid & 31;
    const int wm = wid & 3;            // warp row block (32 rows)
    const int wn = wid >> 2;           // warp col block (64 cols)
    const int g = lane >> 2;
    const int t = lane & 3;

    const int m0 = blockIdx.y * 128;
    const int n0 = blockIdx.x * 128;

    // loader mapping: 2048 16B segs per stage, 8 per thread
    // idx -> mat(2b) | row(7b) | seg(2b)
    const int nch = K / 32;            // 32 chunks

    auto load_chunk = [&](int chunk, int stg) {
        if (chunk < nch) {
            const int koff = chunk * 32;
            const uint32_t sb = sbase + stg * GSTAGE_B;
            #pragma unroll
            for (int s = 0; s < 8; s++) {
                const int idx = s * 256 + tid;
                const int mat = idx >> 9;
                const int within = idx & 511;
                const int row = within >> 2;
                const int seg = within & 3;
                const __nv_bfloat16* base =
                    (mat == 0) ? Ahi : (mat == 1) ? Alo : (mat == 2) ? Whi : Wlo;
                const int grow = (mat < 2 ? m0 : n0) + row;
                cp_async16_s(sb + (uint32_t)(mat * GTILE_B) +
                                 (uint32_t)(row * GLD + seg * 8) * 2,
                             base + (size_t)grow * K + koff + seg * 8);
            }
        }
        cp_commit();  // always commit (uniform group accounting)
    };

    load_chunk(0, 0);
    load_chunk(1, 1);

    float acc[2][8][4];
    #pragma unroll
    for (int i = 0; i < 2; i++)
        #pragma unroll
        for (int j = 0; j < 8; j++)
            #pragma unroll
            for (int e = 0; e < 4; e++) acc[i][j][e] = 0.0f;

    // ldsm lane address components (verified mapping from attention kernel)
    const int arow = (lane & 7) + ((lane >> 3) & 1) * 8;  // A rows
    const int acol = (lane >> 4) * 8;                      // A k cols
    const int b_nrow = (lane & 7) + (lane >> 4) * 8;       // B n rows
    const int b_kcol = ((lane >> 3) & 1) * 8;              // B k cols

    for (int c = 0; c < nch; c++) {
        cp_wait<1>();
        __syncthreads();
        load_chunk(c + 2, (c + 2) % GSTAGES);

        const uint32_t st = sbase + (c % GSTAGES) * GSTAGE_B;
        const uint32_t sAh = st + 0 * GTILE_B;
        const uint32_t sAl = st + 1 * GTILE_B;
        const uint32_t sWh = st + 2 * GTILE_B;
        const uint32_t sWl = st + 3 * GTILE_B;

        #pragma unroll
        for (int ks = 0; ks < 2; ks++) {
            uint32_t ah[2][4], al[2][4];
            #pragma unroll
            for (int i = 0; i < 2; i++) {
                const uint32_t ao =
                    (uint32_t)((wm * 32 + i * 16 + arow) * GLD + ks * 16 + acol) * 2;
                ldsm4(ah[i], sAh + ao);
                ldsm4(al[i], sAl + ao);
            }
            uint32_t bh[4][4], bl[4][4];
            #pragma unroll
            for (int jj = 0; jj < 4; jj++) {
                const uint32_t bo =
                    (uint32_t)((wn * 64 + jj * 16 + b_nrow) * GLD + ks * 16 + b_kcol) * 2;
                ldsm4(bh[jj], sWh + bo);
                ldsm4(bl[jj], sWl + bo);
            }
            #pragma unroll
            for (int i = 0; i < 2; i++)
                #pragma unroll
                for (int jj = 0; jj < 4; jj++) {
                    mma_bf16(acc[i][2 * jj + 0], ah[i], bh[jj][0], bh[jj][1]);
                    mma_bf16(acc[i][2 * jj + 0], ah[i], bl[jj][0], bl[jj][1]);
                    mma_bf16(acc[i][2 * jj + 0], al[i], bh[jj][0], bh[jj][1]);
                    mma_bf16(acc[i][2 * jj + 1], ah[i], bh[jj][2], bh[jj][3]);
                    mma_bf16(acc[i][2 * jj + 1], ah[i], bl[jj][2], bl[jj][3]);
                    mma_bf16(acc[i][2 * jj + 1], al[i], bh[jj][2], bh[jj][3]);
                }
        }
        __syncthreads();
    }

    // ---- epilogue: direct from registers ------------------------------------
    #pragma unroll
    for (int i = 0; i < 2; i++) {
        const int m = m0 + wm * 32 + i * 16 + g;   // rows m, m+8
        if (MODE == 0) {
            #pragma unroll
            for (int j = 0; j < 8; j++) {
                const int n = n0 + wn * 64 + j * 8 + t * 2;
                *(float2*)(O + (size_t)m * Ntot + n) =
                    make_float2(acc[i][j][0], acc[i][j][1]);
                *(float2*)(O + (size_t)(m + 8) * Ntot + n) =
                    make_float2(acc[i][j][2], acc[i][j][3]);
            }
        } else {
            const int b = m >> 11, tt = m & 2047;
            #pragma unroll
            for (int j = 0; j < 8; j++) {
                const int n = n0 + wn * 64 + j * 8 + t * 2;
                const int mat = n >> 10;
                const int within = n & 1023;
                const int hh = within >> 6, dd = within & 63;
                const float sc = (mat == 0) ? QSCALE : 1.0f;
                __nv_bfloat16* hi = (mat == 0) ? Qhi : (mat == 1) ? Khi : Vhi;
                __nv_bfloat16* lo = (mat == 0) ? Qlo : (mat == 1) ? Klo : Vlo;
                const size_t off0 = (((size_t)(b * NHc + hh)) * Tc + tt) * HDc + dd;
                const size_t off1 = off0 + (size_t)8 * HDc;
                const float f0 = acc[i][j][0] * sc, f1 = acc[i][j][1] * sc;
                const float f2 = acc[i][j][2] * sc, f3 = acc[i][j][3] * sc;
                const float h0 = __bfloat162float(__float2bfloat16(f0));
                const float h1 = __bfloat162float(__float2bfloat16(f1));
                const float h2 = __bfloat162float(__float2bfloat16(f2));
                const float h3 = __bfloat162float(__float2bfloat16(f3));
                *(uint32_t*)(hi + off0) = pack_bf16(h0, h1);
                *(uint32_t*)(lo + off0) = pack_bf16(f0 - h0, f1 - h1);
                *(uint32_t*)(hi + off1) = pack_bf16(h2, h3);
                *(uint32_t*)(lo + off1) = pack_bf16(f2 - h2, f3 - h3);
            }
        }
    }
}

// ---------------------------------------------------------------------------
// Register-resident FA2 causal attention (bf16x3) — unchanged from R6.
// ---------------------------------------------------------------------------
#define ALD 72
#define ATB (64 * ALD * 2)
#define ASMEM_BYTES (8 * ATB)

__global__ __launch_bounds__(256, 1) void attn_fa2_kernel(
    const __nv_bfloat16* __restrict__ Qhi, const __nv_bfloat16* __restrict__ Qlo,
    const __nv_bfloat16* __restrict__ Khi_g, const __nv_bfloat16* __restrict__ Klo_g,
    const __nv_bfloat16* __restrict__ Vhi_g, const __nv_bfloat16* __restrict__ Vlo_g,
    __nv_bfloat16* __restrict__ Yhi, __nv_bfloat16* __restrict__ Ylo)
{
    extern __shared__ __align__(16) char asm_[];
    const uint32_t sbase = (uint32_t)__cvta_generic_to_shared(asm_);

    const int tid = threadIdx.x;
    const int w = tid >> 5;
    const int lane = tid & 31;
    const int g = lane >> 2;
    const int t = lane & 3;

    const int qt = (int)gridDim.x - 1 - (int)blockIdx.x;
    const int h = blockIdx.y, b = blockIdx.z;
    const int q0 = qt * 128;

    const size_t bh = (size_t)(b * NHc + h) * Tc;
    const __nv_bfloat16* qhp = Qhi + (bh + q0) * HDc;
    const __nv_bfloat16* qlp = Qlo + (bh + q0) * HDc;
    const __nv_bfloat16* khp = Khi_g + bh * HDc;
    const __nv_bfloat16* klp = Klo_g + bh * HDc;
    const __nv_bfloat16* vhp = Vhi_g + bh * HDc;
    const __nv_bfloat16* vlp = Vlo_g + bh * HDc;

    auto buf = [&](int stg, int mat) -> uint32_t {
        return sbase + (uint32_t)(stg * 4 + mat) * ATB;
    };

    auto load_kv = [&](int kt, int stg) {
        const int k0 = kt * 64;
        #pragma unroll
        for (int s = 0; s < 8; s++) {
            const int idx = s * 256 + tid;
            const int mat = s >> 1;
            const int within = idx & 511;
            const int row = within >> 3;
            const int seg = within & 7;
            const __nv_bfloat16* src =
                (mat == 0 ? khp : mat == 1 ? klp : mat == 2 ? vhp : vlp) +
                (size_t)(k0 + row) * HDc + seg * 8;
            cp_async16_s(buf(stg, mat) + (uint32_t)(row * ALD + seg * 8) * 2, src);
        }
        cp_commit();
    };

    {
        #pragma unroll
        for (int s = 0; s < 8; s++) {
            const int idx = s * 256 + tid;
            const int matq = s >> 2;
            const int within = idx & 1023;
            const int row = within >> 3;
            const int seg = within & 7;
            const __nv_bfloat16* src = (matq ? qlp : qhp) + (size_t)row * HDc + seg * 8;
            const int dstmat = matq * 2 + (row >> 6);
            cp_async16_s(buf(1, dstmat) + (uint32_t)((row & 63) * ALD + seg * 8) * 2, src);
        }
        cp_commit();
    }
    load_kv(0, 0);
    cp_wait<1>();
    __syncthreads();

    uint32_t qh[4][4], ql[4][4];
    {
        const int qrow = w * 16;
        const uint32_t hb = buf(1, qrow < 64 ? 0 : 1);
        const uint32_t lb = buf(1, qrow < 64 ? 2 : 3);
        const int r0 = qrow & 63;
        const int arow = (lane & 7) + ((lane >> 3) & 1) * 8;
        const int acol = (lane >> 4) * 8;
        #pragma unroll
        for (int ks = 0; ks < 4; ks++) {
            ldsm4(qh[ks], hb + (uint32_t)((r0 + arow) * ALD + ks * 16 + acol) * 2);
            ldsm4(ql[ks], lb + (uint32_t)((r0 + arow) * ALD + ks * 16 + acol) * 2);
        }
    }

    float oacc[8][4];
    #pragma unroll
    for (int j = 0; j < 8; j++)
        #pragma unroll
        for (int e = 0; e < 4; e++) oacc[j][e] = 0.0f;
    float m0 = -1e30f, m1 = -1e30f, l0 = 0.0f, l1 = 0.0f;

    const int qrow0 = q0 + w * 16 + g;
    const int qrow1 = qrow0 + 8;
    const int nkt = 2 * qt + 2;

    const int b_nrow = (lane & 7) + (lane >> 4) * 8;
    const int b_kcol = ((lane >> 3) & 1) * 8;
    const int v_krow = (lane & 7) + ((lane >> 3) & 1) * 8;
    const int v_ncol = (lane >> 4) * 8;

    for (int kt = 0; kt < nkt; kt++) {
        cp_wait<0>();
        __syncthreads();
        if (kt + 1 < nkt) load_kv(kt + 1, (kt + 1) & 1);
        const int stg = kt & 1;
        const uint32_t kh_b = buf(stg, 0), kl_b = buf(stg, 1);
        const uint32_t vh_b = buf(stg, 2), vl_b = buf(stg, 3);

        float sacc[8][4];
        #pragma unroll
        for (int j = 0; j < 8; j++)
            #pragma unroll
            for (int e = 0; e < 4; e++) sacc[j][e] = 0.0f;

        #pragma unroll
        for (int ks = 0; ks < 4; ks++) {
            #pragma unroll
            for (int p = 0; p < 4; p++) {
                const uint32_t off =
                    (uint32_t)((p * 16 + b_nrow) * ALD + ks * 16 + b_kcol) * 2;
                uint32_t kh4[4], kl4[4];
                ldsm4(kh4, kh_b + off);
                ldsm4(kl4, kl_b + off);
                mma_bf16(sacc[2 * p + 0], qh[ks], kh4[0], kh4[1]);
                mma_bf16(sacc[2 * p + 0], qh[ks], kl4[0], kl4[1]);
                mma_bf16(sacc[2 * p + 0], ql[ks], kh4[0], kh4[1]);
                mma_bf16(sacc[2 * p + 1], qh[ks], kh4[2], kh4[3]);
                mma_bf16(sacc[2 * p + 1], qh[ks], kl4[2], kl4[3]);
                mma_bf16(sacc[2 * p + 1], ql[ks], kh4[2], kh4[3]);
            }
        }

        if (kt >= 2 * qt) {
            #pragma unroll
            for (int j = 0; j < 8; j++) {
                const int kc = kt * 64 + j * 8 + t * 2;
                if (kc     > qrow0) sacc[j][0] = -1e30f;
                if (kc + 1 > qrow0) sacc[j][1] = -1e30f;
                if (kc     > qrow1) sacc[j][2] = -1e30f;
                if (kc + 1 > qrow1) sacc[j][3] = -1e30f;
            }
        }
        float mx0 = -1e30f, mx1 = -1e30f;
        #pragma unroll
        for (int j = 0; j < 8; j++) {
            mx0 = fmaxf(mx0, fmaxf(sacc[j][0], sacc[j][1]));
            mx1 = fmaxf(mx1, fmaxf(sacc[j][2], sacc[j][3]));
        }
        mx0 = fmaxf(mx0, __shfl_xor_sync(0xffffffffu, mx0, 1));
        mx0 = fmaxf(mx0, __shfl_xor_sync(0xffffffffu, mx0, 2));
        mx1 = fmaxf(mx1, __shfl_xor_sync(0xffffffffu, mx1, 1));
        mx1 = fmaxf(mx1, __shfl_xor_sync(0xffffffffu, mx1, 2));

        const float mn0 = fmaxf(m0, mx0), mn1 = fmaxf(m1, mx1);
        const float c0 = exp2f(m0 - mn0), c1 = exp2f(m1 - mn1);
        m0 = mn0; m1 = mn1;

        uint32_t pah[8][2], pal[8][2];
        float s0 = 0.0f, s1 = 0.0f;
        #pragma unroll
        for (int j = 0; j < 8; j++) {
            const float p0 = exp2f(sacc[j][0] - mn0);
            const float p1 = exp2f(sacc[j][1] - mn0);
            const float p2 = exp2f(sacc[j][2] - mn1);
            const float p3 = exp2f(sacc[j][3] - mn1);
            s0 += p0 + p1; s1 += p2 + p3;
            const float h0 = __bfloat162float(__float2bfloat16(p0));
            const float h1 = __bfloat162float(__float2bfloat16(p1));
            const float h2 = __bfloat162float(__float2bfloat16(p2));
            const float h3 = __bfloat162float(__float2bfloat16(p3));
            pah[j][0] = pack_bf16(h0, h1);
            pah[j][1] = pack_bf16(h2, h3);
            pal[j][0] = pack_bf16(p0 - h0, p1 - h1);
            pal[j][1] = pack_bf16(p2 - h2, p3 - h3);
        }
        l0 = l0 * c0 + s0;
        l1 = l1 * c1 + s1;
        #pragma unroll
        for (int j = 0; j < 8; j++) {
            oacc[j][0] *= c0; oacc[j][1] *= c0;
            oacc[j][2] *= c1; oacc[j][3] *= c1;
        }

        #pragma unroll
        for (int ks = 0; ks < 4; ks++) {
            uint32_t afh[4] = {pah[2 * ks][0], pah[2 * ks][1],
                               pah[2 * ks + 1][0], pah[2 * ks + 1][1]};
            uint32_t afl[4] = {pal[2 * ks][0], pal[2 * ks][1],
                               pal[2 * ks + 1][0], pal[2 * ks + 1][1]};
            #pragma unroll
            for (int p = 0; p < 4; p++) {
                const uint32_t off =
                    (uint32_t)((ks * 16 + v_krow) * ALD + p * 16 + v_ncol) * 2;
                uint32_t vh4[4], vl4[4];
                ldsm4t(vh4, vh_b + off);
                ldsm4t(vl4, vl_b + off);
                mma_bf16(oacc[2 * p + 0], afh, vh4[0], vh4[1]);
                mma_bf16(oacc[2 * p + 0], afh, vl4[0], vl4[1]);
                mma_bf16(oacc[2 * p + 0], afl, vh4[0], vh4[1]);
                mma_bf16(oacc[2 * p + 1], afh, vh4[2], vh4[3]);
                mma_bf16(oacc[2 * p + 1], afh, vl4[2], vl4[3]);
                mma_bf16(oacc[2 * p + 1], afl, vh4[2], vh4[3]);
            }
        }
    }

    l0 += __shfl_xor_sync(0xffffffffu, l0, 1);
    l0 += __shfl_xor_sync(0xffffffffu, l0, 2);
    l1 += __shfl_xor_sync(0xffffffffu, l1, 1);
    l1 += __shfl_xor_sync(0xffffffffu, l1, 2);
    const float i0 = 1.0f / l0, i1 = 1.0f / l1;

    const size_t y0 = ((size_t)b * Tc + qrow0) * Cc + h * HDc + t * 2;
    const size_t y1 = ((size_t)b * Tc + qrow1) * Cc + h * HDc + t * 2;
    #pragma unroll
    for (int j = 0; j < 8; j++) {
        const float f0 = oacc[j][0] * i0, f1 = oacc[j][1] * i0;
        const float f2 = oacc[j][2] * i1, f3 = oacc[j][3] * i1;
        const float h0 = __bfloat162float(__float2bfloat16(f0));
        const float h1 = __bfloat162float(__float2bfloat16(f1));
        const float h2 = __bfloat162float(__float2bfloat16(f2));
        const float h3 = __bfloat162float(__float2bfloat16(f3));
        *(uint32_t*)(Yhi + y0 + j * 8) = pack_bf16(h0, h1);
        *(uint32_t*)(Ylo + y0 + j * 8) = pack_bf16(f0 - h0, f1 - h1);
        *(uint32_t*)(Yhi + y1 + j * 8) = pack_bf16(h2, h3);
        *(uint32_t*)(Ylo + y1 + j * 8) = pack_bf16(f2 - h2, f3 - h3);
    }
}

// ---------------------------------------------------------------------------
extern "C" void kernel_launch(void* const* d_in, const int* in_sizes, int n_in,
                              void* d_out, int out_size)
{
    const float* x  = (const float*)d_in[0];
    const float* Wq = (const float*)d_in[1];
    const float* Wk = (const float*)d_in[2];
    const float* Wv = (const float*)d_in[3];
    const float* Wo = (const float*)d_in[4];
    float* out = (float*)d_out;

    __nv_bfloat16 *qhi, *qlo, *khi, *klo, *vhi, *vlo;
    __nv_bfloat16 *xhi, *xlo, *yhi, *ylo, *whi, *wlo;
    cudaGetSymbolAddress((void**)&qhi, g_qhi);
    cudaGetSymbolAddress((void**)&qlo, g_qlo);
    cudaGetSymbolAddress((void**)&khi, g_khi);
    cudaGetSymbolAddress((void**)&klo, g_klo);
    cudaGetSymbolAddress((void**)&vhi, g_vhi);
    cudaGetSymbolAddress((void**)&vlo, g_vlo);
    cudaGetSymbolAddress((void**)&xhi, g_xhi);
    cudaGetSymbolAddress((void**)&xlo, g_xlo);
    cudaGetSymbolAddress((void**)&yhi, g_yhi);
    cudaGetSymbolAddress((void**)&ylo, g_ylo);
    cudaGetSymbolAddress((void**)&whi, g_whi);
    cudaGetSymbolAddress((void**)&wlo, g_wlo);

    const int M = Bc * Tc;       // 4096
    const int NELX = M * Cc;     // 4 M
    const int NELW = Cc * Cc;    // 1 M

    split_kernel<<<(NELX / 4 + 255) / 256, 256>>>(x, xhi, xlo, NELX / 4);
    split4_kernel<<<(4 * NELW / 4) / 256, 256>>>(Wq, Wk, Wv, Wo, whi, wlo);

    cudaFuncSetAttribute(gemm_mma_kernel<0>,
                         cudaFuncAttributeMaxDynamicSharedMemorySize, GSMEM_BYTES);
    cudaFuncSetAttribute(gemm_mma_kernel<1>,
                         cudaFuncAttributeMaxDynamicSharedMemorySize, GSMEM_BYTES);

    // Fused QKV projection: N = 3072 (Wq|Wk|Wv contiguous in g_whi/g_wlo)
    gemm_mma_kernel<1><<<dim3(3 * Cc / 128, M / 128), 256, GSMEM_BYTES>>>(
        xhi, xlo, whi, wlo, nullptr, 3 * Cc,
        qhi, qlo, khi, klo, vhi, vlo);

    cudaFuncSetAttribute(attn_fa2_kernel,
                         cudaFuncAttributeMaxDynamicSharedMemorySize, ASMEM_BYTES);
    attn_fa2_kernel<<<dim3(Tc / 128, NHc, Bc), 256, ASMEM_BYTES>>>(
        qhi, qlo, khi, klo, vhi, vlo, yhi, ylo);

    // Output projection: fp32 direct
    gemm_mma_kernel<0><<<dim3(Cc / 128, M / 128), 256, GSMEM_BYTES>>>(
        yhi, ylo, whi + 3 * NELW, wlo + 3 * NELW, out, Cc,
        nullptr, nullptr, nullptr, nullptr, nullptr, nullptr);
}

// round 10
// speedup vs baseline: 3.1533x; 1.1131x over previous
#include <cuda_runtime.h>
#include <cuda_bf16.h>
#include <math.h>
#include <stdint.h>

#define Bc  2
#define Tc  2048
#define Cc  1024
#define NHc 16
#define HDc 64

// Q scale: 1/sqrt(64) * log2(e)  (softmax done in exp2 domain)
#define QSCALE 0.18033688011112042f

// ---------------- scratch (device globals; no allocation allowed) ----------
__device__ __nv_bfloat16 g_qhi[Bc * NHc * Tc * HDc];
__device__ __nv_bfloat16 g_qlo[Bc * NHc * Tc * HDc];
__device__ __nv_bfloat16 g_khi[Bc * NHc * Tc * HDc];
__device__ __nv_bfloat16 g_klo[Bc * NHc * Tc * HDc];
__device__ __nv_bfloat16 g_vhi[Bc * NHc * Tc * HDc];
__device__ __nv_bfloat16 g_vlo[Bc * NHc * Tc * HDc];
__device__ __nv_bfloat16 g_xhi[Bc * Tc * Cc];
__device__ __nv_bfloat16 g_xlo[Bc * Tc * Cc];
__device__ __nv_bfloat16 g_yhi[Bc * Tc * Cc];
__device__ __nv_bfloat16 g_ylo[Bc * Tc * Cc];
__device__ __nv_bfloat16 g_whi[4][Cc * Cc];
__device__ __nv_bfloat16 g_wlo[4][Cc * Cc];

// ---------------- fp32 -> bf16 hi/lo splits ---------------------------------
__device__ __forceinline__ void split_store(float vx, float vy, float vz, float vw,
                                            __nv_bfloat16* hi, __nv_bfloat16* lo,
                                            size_t i4)
{
    __nv_bfloat16 h0 = __float2bfloat16(vx), h1 = __float2bfloat16(vy);
    __nv_bfloat16 h2 = __float2bfloat16(vz), h3 = __float2bfloat16(vw);
    __nv_bfloat162* hp = (__nv_bfloat162*)(hi + i4);
    __nv_bfloat162* lp = (__nv_bfloat162*)(lo + i4);
    hp[0] = __nv_bfloat162(h0, h1);
    hp[1] = __nv_bfloat162(h2, h3);
    lp[0] = __nv_bfloat162(__float2bfloat16(vx - __bfloat162float(h0)),
                           __float2bfloat16(vy - __bfloat162float(h1)));
    lp[1] = __nv_bfloat162(__float2bfloat16(vz - __bfloat162float(h2)),
                           __float2bfloat16(vw - __bfloat162float(h3)));
}

__global__ __launch_bounds__(256) void split_kernel(
    const float* __restrict__ x, __nv_bfloat16* __restrict__ hi,
    __nv_bfloat16* __restrict__ lo, int n4)
{
    int i = blockIdx.x * 256 + threadIdx.x;
    if (i < n4) {
        float4 v = ((const float4*)x)[i];
        split_store(v.x, v.y, v.z, v.w, hi, lo, (size_t)i * 4);
    }
}

__global__ __launch_bounds__(256) void split4_kernel(
    const float* __restrict__ w0, const float* __restrict__ w1,
    const float* __restrict__ w2, const float* __restrict__ w3,
    __nv_bfloat16* __restrict__ hi, __nv_bfloat16* __restrict__ lo)
{
    int i = blockIdx.x * 256 + threadIdx.x;       // 0 .. 4*2^18-1
    const int which = i >> 18;
    const int off = i & 262143;
    const float* src = (which == 0) ? w0 : (which == 1) ? w1 : (which == 2) ? w2 : w3;
    float4 v = ((const float4*)src)[off];
    split_store(v.x, v.y, v.z, v.w, hi, lo, (size_t)i * 4);
}

// ---------------- async-copy / mma helpers -----------------------------------
__device__ __forceinline__ void cp_async16_s(uint32_t saddr, const void* g) {
    asm volatile("cp.async.cg.shared.global [%0], [%1], 16;\n" :: "r"(saddr), "l"(g));
}
__device__ __forceinline__ void cp_commit() {
    asm volatile("cp.async.commit_group;\n");
}
template <int N>
__device__ __forceinline__ void cp_wait() {
    asm volatile("cp.async.wait_group %0;\n" :: "n"(N));
}
__device__ __forceinline__ void ldsm4(uint32_t* r, uint32_t a) {
    asm volatile("ldmatrix.sync.aligned.m8n8.x4.shared.b16 {%0,%1,%2,%3}, [%4];"
                 : "=r"(r[0]), "=r"(r[1]), "=r"(r[2]), "=r"(r[3]) : "r"(a));
}
__device__ __forceinline__ void ldsm4t(uint32_t* r, uint32_t a) {
    asm volatile("ldmatrix.sync.aligned.m8n8.x4.trans.shared.b16 {%0,%1,%2,%3}, [%4];"
                 : "=r"(r[0]), "=r"(r[1]), "=r"(r[2]), "=r"(r[3]) : "r"(a));
}
__device__ __forceinline__ void mma_bf16(float* d, const uint32_t* a,
                                         uint32_t b0, uint32_t b1) {
    asm volatile(
        "mma.sync.aligned.m16n8k16.row.col.f32.bf16.bf16.f32 "
        "{%0,%1,%2,%3}, {%4,%5,%6,%7}, {%8,%9}, {%0,%1,%2,%3};"
        : "+f"(d[0]), "+f"(d[1]), "+f"(d[2]), "+f"(d[3])
        : "r"(a[0]), "r"(a[1]), "r"(a[2]), "r"(a[3]), "r"(b0), "r"(b1));
}
__device__ __forceinline__ uint32_t pack_bf16(float a, float b) {
    __nv_bfloat162 h = __floats2bfloat162_rn(a, b);
    return *(uint32_t*)&h;
}

// ---------------------------------------------------------------------------
// bf16x3 NT GEMM (raw mma):  O = A @ W^T,  K = 1024.
// CTA 128x128, 8 warps (4m x 2n), warp tile 32x64. BK=32, 2-stage cp.async,
// 2 CTAs/SM (reg cap 128 via launch_bounds).
// MODE 0: fp32 direct store [M, Ntot].
// MODE 1: fused QKV epilogue (Ntot=3072).
// ---------------------------------------------------------------------------
#define GLD 40                        // halves per padded smem row (80 B)
#define GTILE_B (128 * GLD * 2)       // 10240 B per matrix tile
#define GSTAGE_B (4 * GTILE_B)        // 40960 B  (Ahi,Alo,Whi,Wlo)
#define GSTAGES 2
#define GSMEM_BYTES (GSTAGES * GSTAGE_B)  // 81920

template <int MODE>
__global__ __launch_bounds__(256, 2) void gemm_mma_kernel(
    const __nv_bfloat16* __restrict__ Ahi, const __nv_bfloat16* __restrict__ Alo,
    const __nv_bfloat16* __restrict__ Whi, const __nv_bfloat16* __restrict__ Wlo,
    float* __restrict__ O, int Ntot,
    __nv_bfloat16* __restrict__ Qhi, __nv_bfloat16* __restrict__ Qlo,
    __nv_bfloat16* __restrict__ Khi, __nv_bfloat16* __restrict__ Klo,
    __nv_bfloat16* __restrict__ Vhi, __nv_bfloat16* __restrict__ Vlo)
{
    extern __shared__ __align__(16) char gsm[];
    const uint32_t sbase = (uint32_t)__cvta_generic_to_shared(gsm);
    const int K = Cc;

    const int tid = threadIdx.x;
    const int wid = tid >> 5;
    const int lane = tid & 31;
    const int wm = wid & 3;
    const int wn = wid >> 2;
    const int g = lane >> 2;
    const int t = lane & 3;

    const int m0 = blockIdx.y * 128;
    const int n0 = blockIdx.x * 128;

    const int nch = K / 32;            // 32 chunks

    auto load_chunk = [&](int chunk, int stg) {
        if (chunk < nch) {
            const int koff = chunk * 32;
            const uint32_t sb = sbase + stg * GSTAGE_B;
            #pragma unroll
            for (int s = 0; s < 8; s++) {
                const int idx = s * 256 + tid;
                const int mat = idx >> 9;
                const int within = idx & 511;
                const int row = within >> 2;
                const int seg = within & 3;
                const __nv_bfloat16* base =
                    (mat == 0) ? Ahi : (mat == 1) ? Alo : (mat == 2) ? Whi : Wlo;
                const int grow = (mat < 2 ? m0 : n0) + row;
                cp_async16_s(sb + (uint32_t)(mat * GTILE_B) +
                                 (uint32_t)(row * GLD + seg * 8) * 2,
                             base + (size_t)grow * K + koff + seg * 8);
            }
        }
        cp_commit();  // uniform group accounting
    };

    load_chunk(0, 0);

    float acc[2][8][4];
    #pragma unroll
    for (int i = 0; i < 2; i++)
        #pragma unroll
        for (int j = 0; j < 8; j++)
            #pragma unroll
            for (int e = 0; e < 4; e++) acc[i][j][e] = 0.0f;

    const int arow = (lane & 7) + ((lane >> 3) & 1) * 8;
    const int acol = (lane >> 4) * 8;
    const int b_nrow = (lane & 7) + (lane >> 4) * 8;
    const int b_kcol = ((lane >> 3) & 1) * 8;

    for (int c = 0; c < nch; c++) {
        load_chunk(c + 1, (c + 1) & 1);   // other stage: chunk c-1 already consumed
        cp_wait<1>();                      // chunk c resident
        __syncthreads();

        const uint32_t st = sbase + (c & 1) * GSTAGE_B;
        const uint32_t sAh = st + 0 * GTILE_B;
        const uint32_t sAl = st + 1 * GTILE_B;
        const uint32_t sWh = st + 2 * GTILE_B;
        const uint32_t sWl = st + 3 * GTILE_B;

        #pragma unroll
        for (int ks = 0; ks < 2; ks++) {
            uint32_t ah[2][4], al[2][4];
            #pragma unroll
            for (int i = 0; i < 2; i++) {
                const uint32_t ao =
                    (uint32_t)((wm * 32 + i * 16 + arow) * GLD + ks * 16 + acol) * 2;
                ldsm4(ah[i], sAh + ao);
                ldsm4(al[i], sAl + ao);
            }
            #pragma unroll
            for (int jj = 0; jj < 4; jj++) {
                const uint32_t bo =
                    (uint32_t)((wn * 64 + jj * 16 + b_nrow) * GLD + ks * 16 + b_kcol) * 2;
                uint32_t bh[4], bl[4];
                ldsm4(bh, sWh + bo);
                ldsm4(bl, sWl + bo);
                #pragma unroll
                for (int i = 0; i < 2; i++) {
                    mma_bf16(acc[i][2 * jj + 0], ah[i], bh[0], bh[1]);
                    mma_bf16(acc[i][2 * jj + 0], ah[i], bl[0], bl[1]);
                    mma_bf16(acc[i][2 * jj + 0], al[i], bh[0], bh[1]);
                    mma_bf16(acc[i][2 * jj + 1], ah[i], bh[2], bh[3]);
                    mma_bf16(acc[i][2 * jj + 1], ah[i], bl[2], bl[3]);
                    mma_bf16(acc[i][2 * jj + 1], al[i], bh[2], bh[3]);
                }
            }
        }
        __syncthreads();
    }

    // ---- epilogue: direct from registers ------------------------------------
    #pragma unroll
    for (int i = 0; i < 2; i++) {
        const int m = m0 + wm * 32 + i * 16 + g;   // rows m, m+8
        if (MODE == 0) {
            #pragma unroll
            for (int j = 0; j < 8; j++) {
                const int n = n0 + wn * 64 + j * 8 + t * 2;
                *(float2*)(O + (size_t)m * Ntot + n) =
                    make_float2(acc[i][j][0], acc[i][j][1]);
                *(float2*)(O + (size_t)(m + 8) * Ntot + n) =
                    make_float2(acc[i][j][2], acc[i][j][3]);
            }
        } else {
            const int b = m >> 11, tt = m & 2047;
            #pragma unroll
            for (int j = 0; j < 8; j++) {
                const int n = n0 + wn * 64 + j * 8 + t * 2;
                const int mat = n >> 10;
                const int within = n & 1023;
                const int hh = within >> 6, dd = within & 63;
                const float sc = (mat == 0) ? QSCALE : 1.0f;
                __nv_bfloat16* hi = (mat == 0) ? Qhi : (mat == 1) ? Khi : Vhi;
                __nv_bfloat16* lo = (mat == 0) ? Qlo : (mat == 1) ? Klo : Vlo;
                const size_t off0 = (((size_t)(b * NHc + hh)) * Tc + tt) * HDc + dd;
                const size_t off1 = off0 + (size_t)8 * HDc;
                const float f0 = acc[i][j][0] * sc, f1 = acc[i][j][1] * sc;
                const float f2 = acc[i][j][2] * sc, f3 = acc[i][j][3] * sc;
                const float h0 = __bfloat162float(__float2bfloat16(f0));
                const float h1 = __bfloat162float(__float2bfloat16(f1));
                const float h2 = __bfloat162float(__float2bfloat16(f2));
                const float h3 = __bfloat162float(__float2bfloat16(f3));
                *(uint32_t*)(hi + off0) = pack_bf16(h0, h1);
                *(uint32_t*)(lo + off0) = pack_bf16(f0 - h0, f1 - h1);
                *(uint32_t*)(hi + off1) = pack_bf16(h2, h3);
                *(uint32_t*)(lo + off1) = pack_bf16(f2 - h2, f3 - h3);
            }
        }
    }
}

// ---------------------------------------------------------------------------
// Register-resident FA2 causal attention (bf16x3 throughout) — R7-verified.
// ---------------------------------------------------------------------------
#define ALD 72
#define ATB (64 * ALD * 2)
#define ASMEM_BYTES (8 * ATB)

__global__ __launch_bounds__(256, 1) void attn_fa2_kernel(
    const __nv_bfloat16* __restrict__ Qhi, const __nv_bfloat16* __restrict__ Qlo,
    const __nv_bfloat16* __restrict__ Khi_g, const __nv_bfloat16* __restrict__ Klo_g,
    const __nv_bfloat16* __restrict__ Vhi_g, const __nv_bfloat16* __restrict__ Vlo_g,
    __nv_bfloat16* __restrict__ Yhi, __nv_bfloat16* __restrict__ Ylo)
{
    extern __shared__ __align__(16) char asm_[];
    const uint32_t sbase = (uint32_t)__cvta_generic_to_shared(asm_);

    const int tid = threadIdx.x;
    const int w = tid >> 5;
    const int lane = tid & 31;
    const int g = lane >> 2;
    const int t = lane & 3;

    const int qt = (int)gridDim.x - 1 - (int)blockIdx.x;
    const int h = blockIdx.y, b = blockIdx.z;
    const int q0 = qt * 128;

    const size_t bh = (size_t)(b * NHc + h) * Tc;
    const __nv_bfloat16* qhp = Qhi + (bh + q0) * HDc;
    const __nv_bfloat16* qlp = Qlo + (bh + q0) * HDc;
    const __nv_bfloat16* khp = Khi_g + bh * HDc;
    const __nv_bfloat16* klp = Klo_g + bh * HDc;
    const __nv_bfloat16* vhp = Vhi_g + bh * HDc;
    const __nv_bfloat16* vlp = Vlo_g + bh * HDc;

    auto buf = [&](int stg, int mat) -> uint32_t {
        return sbase + (uint32_t)(stg * 4 + mat) * ATB;
    };

    auto load_kv = [&](int kt, int stg) {
        const int k0 = kt * 64;
        #pragma unroll
        for (int s = 0; s < 8; s++) {
            const int idx = s * 256 + tid;
            const int mat = s >> 1;
            const int within = idx & 511;
            const int row = within >> 3;
            const int seg = within & 7;
            const __nv_bfloat16* src =
                (mat == 0 ? khp : mat == 1 ? klp : mat == 2 ? vhp : vlp) +
                (size_t)(k0 + row) * HDc + seg * 8;
            cp_async16_s(buf(stg, mat) + (uint32_t)(row * ALD + seg * 8) * 2, src);
        }
        cp_commit();
    };

    {
        #pragma unroll
        for (int s = 0; s < 8; s++) {
            const int idx = s * 256 + tid;
            const int matq = s >> 2;
            const int within = idx & 1023;
            const int row = within >> 3;
            const int seg = within & 7;
            const __nv_bfloat16* src = (matq ? qlp : qhp) + (size_t)row * HDc + seg * 8;
            const int dstmat = matq * 2 + (row >> 6);
            cp_async16_s(buf(1, dstmat) + (uint32_t)((row & 63) * ALD + seg * 8) * 2, src);
        }
        cp_commit();
    }
    load_kv(0, 0);
    cp_wait<1>();
    __syncthreads();

    uint32_t qh[4][4], ql[4][4];
    {
        const int qrow = w * 16;
        const uint32_t hb = buf(1, qrow < 64 ? 0 : 1);
        const uint32_t lb = buf(1, qrow < 64 ? 2 : 3);
        const int r0 = qrow & 63;
        const int arow = (lane & 7) + ((lane >> 3) & 1) * 8;
        const int acol = (lane >> 4) * 8;
        #pragma unroll
        for (int ks = 0; ks < 4; ks++) {
            ldsm4(qh[ks], hb + (uint32_t)((r0 + arow) * ALD + ks * 16 + acol) * 2);
            ldsm4(ql[ks], lb + (uint32_t)((r0 + arow) * ALD + ks * 16 + acol) * 2);
        }
    }

    float oacc[8][4];
    #pragma unroll
    for (int j = 0; j < 8; j++)
        #pragma unroll
        for (int e = 0; e < 4; e++) oacc[j][e] = 0.0f;
    float m0 = -1e30f, m1 = -1e30f, l0 = 0.0f, l1 = 0.0f;

    const int qrow0 = q0 + w * 16 + g;
    const int qrow1 = qrow0 + 8;
    const int nkt = 2 * qt + 2;

    const int b_nrow = (lane & 7) + (lane >> 4) * 8;
    const int b_kcol = ((lane >> 3) & 1) * 8;
    const int v_krow = (lane & 7) + ((lane >> 3) & 1) * 8;
    const int v_ncol = (lane >> 4) * 8;

    for (int kt = 0; kt < nkt; kt++) {
        cp_wait<0>();
        __syncthreads();
        if (kt + 1 < nkt) load_kv(kt + 1, (kt + 1) & 1);
        const int stg = kt & 1;
        const uint32_t kh_b = buf(stg, 0), kl_b = buf(stg, 1);
        const uint32_t vh_b = buf(stg, 2), vl_b = buf(stg, 3);

        float sacc[8][4];
        #pragma unroll
        for (int j = 0; j < 8; j++)
            #pragma unroll
            for (int e = 0; e < 4; e++) sacc[j][e] = 0.0f;

        #pragma unroll
        for (int ks = 0; ks < 4; ks++) {
            #pragma unroll
            for (int p = 0; p < 4; p++) {
                const uint32_t off =
                    (uint32_t)((p * 16 + b_nrow) * ALD + ks * 16 + b_kcol) * 2;
                uint32_t kh4[4], kl4[4];
                ldsm4(kh4, kh_b + off);
                ldsm4(kl4, kl_b + off);
                mma_bf16(sacc[2 * p + 0], qh[ks], kh4[0], kh4[1]);
                mma_bf16(sacc[2 * p + 0], qh[ks], kl4[0], kl4[1]);
                mma_bf16(sacc[2 * p + 0], ql[ks], kh4[0], kh4[1]);
                mma_bf16(sacc[2 * p + 1], qh[ks], kh4[2], kh4[3]);
                mma_bf16(sacc[2 * p + 1], qh[ks], kl4[2], kl4[3]);
                mma_bf16(sacc[2 * p + 1], ql[ks], kh4[2], kh4[3]);
            }
        }

        if (kt >= 2 * qt) {
            #pragma unroll
            for (int j = 0; j < 8; j++) {
                const int kc = kt * 64 + j * 8 + t * 2;
                if (kc     > qrow0) sacc[j][0] = -1e30f;
                if (kc + 1 > qrow0) sacc[j][1] = -1e30f;
                if (kc     > qrow1) sacc[j][2] = -1e30f;
                if (kc + 1 > qrow1) sacc[j][3] = -1e30f;
            }
        }
        float mx0 = -1e30f, mx1 = -1e30f;
        #pragma unroll
        for (int j = 0; j < 8; j++) {
            mx0 = fmaxf(mx0, fmaxf(sacc[j][0], sacc[j][1]));
            mx1 = fmaxf(mx1, fmaxf(sacc[j][2], sacc[j][3]));
        }
        mx0 = fmaxf(mx0, __shfl_xor_sync(0xffffffffu, mx0, 1));
        mx0 = fmaxf(mx0, __shfl_xor_sync(0xffffffffu, mx0, 2));
        mx1 = fmaxf(mx1, __shfl_xor_sync(0xffffffffu, mx1, 1));
        mx1 = fmaxf(mx1, __shfl_xor_sync(0xffffffffu, mx1, 2));

        const float mn0 = fmaxf(m0, mx0), mn1 = fmaxf(m1, mx1);
        const float c0 = exp2f(m0 - mn0), c1 = exp2f(m1 - mn1);
        m0 = mn0; m1 = mn1;

        uint32_t pah[8][2], pal[8][2];
        float s0 = 0.0f, s1 = 0.0f;
        #pragma unroll
        for (int j = 0; j < 8; j++) {
            const float p0 = exp2f(sacc[j][0] - mn0);
            const float p1 = exp2f(sacc[j][1] - mn0);
            const float p2 = exp2f(sacc[j][2] - mn1);
            const float p3 = exp2f(sacc[j][3] - mn1);
            s0 += p0 + p1; s1 += p2 + p3;
            const float h0 = __bfloat162float(__float2bfloat16(p0));
            const float h1 = __bfloat162float(__float2bfloat16(p1));
            const float h2 = __bfloat162float(__float2bfloat16(p2));
            const float h3 = __bfloat162float(__float2bfloat16(p3));
            pah[j][0] = pack_bf16(h0, h1);
            pah[j][1] = pack_bf16(h2, h3);
            pal[j][0] = pack_bf16(p0 - h0, p1 - h1);
            pal[j][1] = pack_bf16(p2 - h2, p3 - h3);
        }
        l0 = l0 * c0 + s0;
        l1 = l1 * c1 + s1;
        #pragma unroll
        for (int j = 0; j < 8; j++) {
            oacc[j][0] *= c0; oacc[j][1] *= c0;
            oacc[j][2] *= c1; oacc[j][3] *= c1;
        }

        // O += P V  (full bf16x3: Phi*Vhi + Phi*Vlo + Plo*Vhi)
        #pragma unroll
        for (int ks = 0; ks < 4; ks++) {
            uint32_t afh[4] = {pah[2 * ks][0], pah[2 * ks][1],
                               pah[2 * ks + 1][0], pah[2 * ks + 1][1]};
            uint32_t afl[4] = {pal[2 * ks][0], pal[2 * ks][1],
                               pal[2 * ks + 1][0], pal[2 * ks + 1][1]};
            #pragma unroll
            for (int p = 0; p < 4; p++) {
                const uint32_t off =
                    (uint32_t)((ks * 16 + v_krow) * ALD + p * 16 + v_ncol) * 2;
                uint32_t vh4[4], vl4[4];
                ldsm4t(vh4, vh_b + off);
                ldsm4t(vl4, vl_b + off);
                mma_bf16(oacc[2 * p + 0], afh, vh4[0], vh4[1]);
                mma_bf16(oacc[2 * p + 0], afh, vl4[0], vl4[1]);
                mma_bf16(oacc[2 * p + 0], afl, vh4[0], vh4[1]);
                mma_bf16(oacc[2 * p + 1], afh, vh4[2], vh4[3]);
                mma_bf16(oacc[2 * p + 1], afh, vl4[2], vl4[3]);
                mma_bf16(oacc[2 * p + 1], afl, vh4[2], vh4[3]);
            }
        }
    }

    l0 += __shfl_xor_sync(0xffffffffu, l0, 1);
    l0 += __shfl_xor_sync(0xffffffffu, l0, 2);
    l1 += __shfl_xor_sync(0xffffffffu, l1, 1);
    l1 += __shfl_xor_sync(0xffffffffu, l1, 2);
    const float i0 = 1.0f / l0, i1 = 1.0f / l1;

    const size_t y0 = ((size_t)b * Tc + qrow0) * Cc + h * HDc + t * 2;
    const size_t y1 = ((size_t)b * Tc + qrow1) * Cc + h * HDc + t * 2;
    #pragma unroll
    for (int j = 0; j < 8; j++) {
        const float f0 = oacc[j][0] * i0, f1 = oacc[j][1] * i0;
        const float f2 = oacc[j][2] * i1, f3 = oacc[j][3] * i1;
        const float h0 = __bfloat162float(__float2bfloat16(f0));
        const float h1 = __bfloat162float(__float2bfloat16(f1));
        const float h2 = __bfloat162float(__float2bfloat16(f2));
        const float h3 = __bfloat162float(__float2bfloat16(f3));
        *(uint32_t*)(Yhi + y0 + j * 8) = pack_bf16(h0, h1);
        *(uint32_t*)(Ylo + y0 + j * 8) = pack_bf16(f0 - h0, f1 - h1);
        *(uint32_t*)(Yhi + y1 + j * 8) = pack_bf16(h2, h3);
        *(uint32_t*)(Ylo + y1 + j * 8) = pack_bf16(f2 - h2, f3 - h3);
    }
}

// ---------------------------------------------------------------------------
extern "C" void kernel_launch(void* const* d_in, const int* in_sizes, int n_in,
                              void* d_out, int out_size)
{
    const float* x  = (const float*)d_in[0];
    const float* Wq = (const float*)d_in[1];
    const float* Wk = (const float*)d_in[2];
    const float* Wv = (const float*)d_in[3];
    const float* Wo = (const float*)d_in[4];
    float* out = (float*)d_out;

    __nv_bfloat16 *qhi, *qlo, *khi, *klo, *vhi, *vlo;
    __nv_bfloat16 *xhi, *xlo, *yhi, *ylo, *whi, *wlo;
    cudaGetSymbolAddress((void**)&qhi, g_qhi);
    cudaGetSymbolAddress((void**)&qlo, g_qlo);
    cudaGetSymbolAddress((void**)&khi, g_khi);
    cudaGetSymbolAddress((void**)&klo, g_klo);
    cudaGetSymbolAddress((void**)&vhi, g_vhi);
    cudaGetSymbolAddress((void**)&vlo, g_vlo);
    cudaGetSymbolAddress((void**)&xhi, g_xhi);
    cudaGetSymbolAddress((void**)&xlo, g_xlo);
    cudaGetSymbolAddress((void**)&yhi, g_yhi);
    cudaGetSymbolAddress((void**)&ylo, g_ylo);
    cudaGetSymbolAddress((void**)&whi, g_whi);
    cudaGetSymbolAddress((void**)&wlo, g_wlo);

    const int M = Bc * Tc;       // 4096
    const int NELX = M * Cc;     // 4 M
    const int NELW = Cc * Cc;    // 1 M

    split_kernel<<<(NELX / 4 + 255) / 256, 256>>>(x, xhi, xlo, NELX / 4);
    split4_kernel<<<(4 * NELW / 4) / 256, 256>>>(Wq, Wk, Wv, Wo, whi, wlo);

    cudaFuncSetAttribute(gemm_mma_kernel<0>,
                         cudaFuncAttributeMaxDynamicSharedMemorySize, GSMEM_BYTES);
    cudaFuncSetAttribute(gemm_mma_kernel<1>,
                         cudaFuncAttributeMaxDynamicSharedMemorySize, GSMEM_BYTES);

    // Fused QKV projection: N = 3072 (Wq|Wk|Wv contiguous in g_whi/g_wlo)
    gemm_mma_kernel<1><<<dim3(3 * Cc / 128, M / 128), 256, GSMEM_BYTES>>>(
        xhi, xlo, whi, wlo, nullptr, 3 * Cc,
        qhi, qlo, khi, klo, vhi, vlo);

    cudaFuncSetAttribute(attn_fa2_kernel,
                         cudaFuncAttributeMaxDynamicSharedMemorySize, ASMEM_BYTES);
    attn_fa2_kernel<<<dim3(Tc / 128, NHc, Bc), 256, ASMEM_BYTES>>>(
        qhi, qlo, khi, klo, vhi, vlo, yhi, ylo);

    // Output projection: fp32 direct
    gemm_mma_kernel<0><<<dim3(Cc / 128, M / 128), 256, GSMEM_BYTES>>>(
        yhi, ylo, whi + 3 * NELW, wlo + 3 * NELW, out, Cc,
        nullptr, nullptr, nullptr, nullptr, nullptr, nullptr);
}

// round 11
// speedup vs baseline: 3.1858x; 1.0103x over previous
#include <cuda_runtime.h>
#include <cuda_bf16.h>
#include <math.h>
#include <stdint.h>

#define Bc  2
#define Tc  2048
#define Cc  1024
#define NHc 16
#define HDc 64

// Q scale: 1/sqrt(64) * log2(e)  (softmax done in exp2 domain)
#define QSCALE 0.18033688011112042f

// ---------------- scratch (device globals; no allocation allowed) ----------
__device__ __nv_bfloat16 g_qhi[Bc * NHc * Tc * HDc];
__device__ __nv_bfloat16 g_qlo[Bc * NHc * Tc * HDc];
__device__ __nv_bfloat16 g_khi[Bc * NHc * Tc * HDc];
__device__ __nv_bfloat16 g_klo[Bc * NHc * Tc * HDc];
__device__ __nv_bfloat16 g_vhi[Bc * NHc * Tc * HDc];
__device__ __nv_bfloat16 g_vlo[Bc * NHc * Tc * HDc];
__device__ __nv_bfloat16 g_xhi[Bc * Tc * Cc];
__device__ __nv_bfloat16 g_xlo[Bc * Tc * Cc];
__device__ __nv_bfloat16 g_yhi[Bc * Tc * Cc];
__device__ __nv_bfloat16 g_ylo[Bc * Tc * Cc];
__device__ __nv_bfloat16 g_whi[4][Cc * Cc];
__device__ __nv_bfloat16 g_wlo[4][Cc * Cc];

// ---------------- fp32 -> bf16 hi/lo splits ---------------------------------
__device__ __forceinline__ void split_store(float vx, float vy, float vz, float vw,
                                            __nv_bfloat16* hi, __nv_bfloat16* lo,
                                            size_t i4)
{
    __nv_bfloat16 h0 = __float2bfloat16(vx), h1 = __float2bfloat16(vy);
    __nv_bfloat16 h2 = __float2bfloat16(vz), h3 = __float2bfloat16(vw);
    __nv_bfloat162* hp = (__nv_bfloat162*)(hi + i4);
    __nv_bfloat162* lp = (__nv_bfloat162*)(lo + i4);
    hp[0] = __nv_bfloat162(h0, h1);
    hp[1] = __nv_bfloat162(h2, h3);
    lp[0] = __nv_bfloat162(__float2bfloat16(vx - __bfloat162float(h0)),
                           __float2bfloat16(vy - __bfloat162float(h1)));
    lp[1] = __nv_bfloat162(__float2bfloat16(vz - __bfloat162float(h2)),
                           __float2bfloat16(vw - __bfloat162float(h3)));
}

__global__ __launch_bounds__(256) void split_kernel(
    const float* __restrict__ x, __nv_bfloat16* __restrict__ hi,
    __nv_bfloat16* __restrict__ lo, int n4)
{
    int i = blockIdx.x * 256 + threadIdx.x;
    if (i < n4) {
        float4 v = ((const float4*)x)[i];
        split_store(v.x, v.y, v.z, v.w, hi, lo, (size_t)i * 4);
    }
}

__global__ __launch_bounds__(256) void split4_kernel(
    const float* __restrict__ w0, const float* __restrict__ w1,
    const float* __restrict__ w2, const float* __restrict__ w3,
    __nv_bfloat16* __restrict__ hi, __nv_bfloat16* __restrict__ lo)
{
    int i = blockIdx.x * 256 + threadIdx.x;       // 0 .. 4*2^18-1
    const int which = i >> 18;
    const int off = i & 262143;
    const float* src = (which == 0) ? w0 : (which == 1) ? w1 : (which == 2) ? w2 : w3;
    float4 v = ((const float4*)src)[off];
    split_store(v.x, v.y, v.z, v.w, hi, lo, (size_t)i * 4);
}

// ---------------- async-copy / mma helpers -----------------------------------
__device__ __forceinline__ void cp_async16_s(uint32_t saddr, const void* g) {
    asm volatile("cp.async.cg.shared.global [%0], [%1], 16;\n" :: "r"(saddr), "l"(g));
}
__device__ __forceinline__ void cp_commit() {
    asm volatile("cp.async.commit_group;\n");
}
template <int N>
__device__ __forceinline__ void cp_wait() {
    asm volatile("cp.async.wait_group %0;\n" :: "n"(N));
}
__device__ __forceinline__ void ldsm4(uint32_t* r, uint32_t a) {
    asm volatile("ldmatrix.sync.aligned.m8n8.x4.shared.b16 {%0,%1,%2,%3}, [%4];"
                 : "=r"(r[0]), "=r"(r[1]), "=r"(r[2]), "=r"(r[3]) : "r"(a));
}
__device__ __forceinline__ void ldsm4t(uint32_t* r, uint32_t a) {
    asm volatile("ldmatrix.sync.aligned.m8n8.x4.trans.shared.b16 {%0,%1,%2,%3}, [%4];"
                 : "=r"(r[0]), "=r"(r[1]), "=r"(r[2]), "=r"(r[3]) : "r"(a));
}
__device__ __forceinline__ void mma_bf16(float* d, const uint32_t* a,
                                         uint32_t b0, uint32_t b1) {
    asm volatile(
        "mma.sync.aligned.m16n8k16.row.col.f32.bf16.bf16.f32 "
        "{%0,%1,%2,%3}, {%4,%5,%6,%7}, {%8,%9}, {%0,%1,%2,%3};"
        : "+f"(d[0]), "+f"(d[1]), "+f"(d[2]), "+f"(d[3])
        : "r"(a[0]), "r"(a[1]), "r"(a[2]), "r"(a[3]), "r"(b0), "r"(b1));
}
__device__ __forceinline__ uint32_t pack_bf16(float a, float b) {
    __nv_bfloat162 h = __floats2bfloat162_rn(a, b);
    return *(uint32_t*)&h;
}

// ---------------------------------------------------------------------------
// bf16x3 NT GEMM (raw mma) — unchanged from R9 (2 CTAs/SM).
// ---------------------------------------------------------------------------
#define GLD 40                        // halves per padded smem row (80 B)
#define GTILE_B (128 * GLD * 2)       // 10240 B per matrix tile
#define GSTAGE_B (4 * GTILE_B)        // 40960 B  (Ahi,Alo,Whi,Wlo)
#define GSTAGES 2
#define GSMEM_BYTES (GSTAGES * GSTAGE_B)  // 81920

template <int MODE>
__global__ __launch_bounds__(256, 2) void gemm_mma_kernel(
    const __nv_bfloat16* __restrict__ Ahi, const __nv_bfloat16* __restrict__ Alo,
    const __nv_bfloat16* __restrict__ Whi, const __nv_bfloat16* __restrict__ Wlo,
    float* __restrict__ O, int Ntot,
    __nv_bfloat16* __restrict__ Qhi, __nv_bfloat16* __restrict__ Qlo,
    __nv_bfloat16* __restrict__ Khi, __nv_bfloat16* __restrict__ Klo,
    __nv_bfloat16* __restrict__ Vhi, __nv_bfloat16* __restrict__ Vlo)
{
    extern __shared__ __align__(16) char gsm[];
    const uint32_t sbase = (uint32_t)__cvta_generic_to_shared(gsm);
    const int K = Cc;

    const int tid = threadIdx.x;
    const int wid = tid >> 5;
    const int lane = tid & 31;
    const int wm = wid & 3;
    const int wn = wid >> 2;
    const int g = lane >> 2;
    const int t = lane & 3;

    const int m0 = blockIdx.y * 128;
    const int n0 = blockIdx.x * 128;

    const int nch = K / 32;            // 32 chunks

    auto load_chunk = [&](int chunk, int stg) {
        if (chunk < nch) {
            const int koff = chunk * 32;
            const uint32_t sb = sbase + stg * GSTAGE_B;
            #pragma unroll
            for (int s = 0; s < 8; s++) {
                const int idx = s * 256 + tid;
                const int mat = idx >> 9;
                const int within = idx & 511;
                const int row = within >> 2;
                const int seg = within & 3;
                const __nv_bfloat16* base =
                    (mat == 0) ? Ahi : (mat == 1) ? Alo : (mat == 2) ? Whi : Wlo;
                const int grow = (mat < 2 ? m0 : n0) + row;
                cp_async16_s(sb + (uint32_t)(mat * GTILE_B) +
                                 (uint32_t)(row * GLD + seg * 8) * 2,
                             base + (size_t)grow * K + koff + seg * 8);
            }
        }
        cp_commit();  // uniform group accounting
    };

    load_chunk(0, 0);

    float acc[2][8][4];
    #pragma unroll
    for (int i = 0; i < 2; i++)
        #pragma unroll
        for (int j = 0; j < 8; j++)
            #pragma unroll
            for (int e = 0; e < 4; e++) acc[i][j][e] = 0.0f;

    const int arow = (lane & 7) + ((lane >> 3) & 1) * 8;
    const int acol = (lane >> 4) * 8;
    const int b_nrow = (lane & 7) + (lane >> 4) * 8;
    const int b_kcol = ((lane >> 3) & 1) * 8;

    for (int c = 0; c < nch; c++) {
        load_chunk(c + 1, (c + 1) & 1);
        cp_wait<1>();
        __syncthreads();

        const uint32_t st = sbase + (c & 1) * GSTAGE_B;
        const uint32_t sAh = st + 0 * GTILE_B;
        const uint32_t sAl = st + 1 * GTILE_B;
        const uint32_t sWh = st + 2 * GTILE_B;
        const uint32_t sWl = st + 3 * GTILE_B;

        #pragma unroll
        for (int ks = 0; ks < 2; ks++) {
            uint32_t ah[2][4], al[2][4];
            #pragma unroll
            for (int i = 0; i < 2; i++) {
                const uint32_t ao =
                    (uint32_t)((wm * 32 + i * 16 + arow) * GLD + ks * 16 + acol) * 2;
                ldsm4(ah[i], sAh + ao);
                ldsm4(al[i], sAl + ao);
            }
            #pragma unroll
            for (int jj = 0; jj < 4; jj++) {
                const uint32_t bo =
                    (uint32_t)((wn * 64 + jj * 16 + b_nrow) * GLD + ks * 16 + b_kcol) * 2;
                uint32_t bh[4], bl[4];
                ldsm4(bh, sWh + bo);
                ldsm4(bl, sWl + bo);
                #pragma unroll
                for (int i = 0; i < 2; i++) {
                    mma_bf16(acc[i][2 * jj + 0], ah[i], bh[0], bh[1]);
                    mma_bf16(acc[i][2 * jj + 0], ah[i], bl[0], bl[1]);
                    mma_bf16(acc[i][2 * jj + 0], al[i], bh[0], bh[1]);
                    mma_bf16(acc[i][2 * jj + 1], ah[i], bh[2], bh[3]);
                    mma_bf16(acc[i][2 * jj + 1], ah[i], bl[2], bl[3]);
                    mma_bf16(acc[i][2 * jj + 1], al[i], bh[2], bh[3]);
                }
            }
        }
        __syncthreads();
    }

    // ---- epilogue: direct from registers ------------------------------------
    #pragma unroll
    for (int i = 0; i < 2; i++) {
        const int m = m0 + wm * 32 + i * 16 + g;   // rows m, m+8
        if (MODE == 0) {
            #pragma unroll
            for (int j = 0; j < 8; j++) {
                const int n = n0 + wn * 64 + j * 8 + t * 2;
                *(float2*)(O + (size_t)m * Ntot + n) =
                    make_float2(acc[i][j][0], acc[i][j][1]);
                *(float2*)(O + (size_t)(m + 8) * Ntot + n) =
                    make_float2(acc[i][j][2], acc[i][j][3]);
            }
        } else {
            const int b = m >> 11, tt = m & 2047;
            #pragma unroll
            for (int j = 0; j < 8; j++) {
                const int n = n0 + wn * 64 + j * 8 + t * 2;
                const int mat = n >> 10;
                const int within = n & 1023;
                const int hh = within >> 6, dd = within & 63;
                const float sc = (mat == 0) ? QSCALE : 1.0f;
                __nv_bfloat16* hi = (mat == 0) ? Qhi : (mat == 1) ? Khi : Vhi;
                __nv_bfloat16* lo = (mat == 0) ? Qlo : (mat == 1) ? Klo : Vlo;
                const size_t off0 = (((size_t)(b * NHc + hh)) * Tc + tt) * HDc + dd;
                const size_t off1 = off0 + (size_t)8 * HDc;
                const float f0 = acc[i][j][0] * sc, f1 = acc[i][j][1] * sc;
                const float f2 = acc[i][j][2] * sc, f3 = acc[i][j][3] * sc;
                const float h0 = __bfloat162float(__float2bfloat16(f0));
                const float h1 = __bfloat162float(__float2bfloat16(f1));
                const float h2 = __bfloat162float(__float2bfloat16(f2));
                const float h3 = __bfloat162float(__float2bfloat16(f3));
                *(uint32_t*)(hi + off0) = pack_bf16(h0, h1);
                *(uint32_t*)(lo + off0) = pack_bf16(f0 - h0, f1 - h1);
                *(uint32_t*)(hi + off1) = pack_bf16(h2, h3);
                *(uint32_t*)(lo + off1) = pack_bf16(f2 - h2, f3 - h3);
            }
        }
    }
}

// ---------------------------------------------------------------------------
// Register-resident FA2 causal attention (bf16x3 throughout).
// CTA: 64 q rows, 4 warps x 16 rows, 128 threads, 3 CTAs/SM.
// kv tiles of 64, double-buffered cp.async. Per-warp math identical to R7.
// ---------------------------------------------------------------------------
#define ALD 72
#define ATB (64 * ALD * 2)
#define ASMEM_BYTES (8 * ATB)     // 73728

__global__ __launch_bounds__(128, 3) void attn_fa2_kernel(
    const __nv_bfloat16* __restrict__ Qhi, const __nv_bfloat16* __restrict__ Qlo,
    const __nv_bfloat16* __restrict__ Khi_g, const __nv_bfloat16* __restrict__ Klo_g,
    const __nv_bfloat16* __restrict__ Vhi_g, const __nv_bfloat16* __restrict__ Vlo_g,
    __nv_bfloat16* __restrict__ Yhi, __nv_bfloat16* __restrict__ Ylo)
{
    extern __shared__ __align__(16) char asm_[];
    const uint32_t sbase = (uint32_t)__cvta_generic_to_shared(asm_);

    const int tid = threadIdx.x;
    const int w = tid >> 5;        // 0..3
    const int lane = tid & 31;
    const int g = lane >> 2;
    const int t = lane & 3;

    const int qt = (int)gridDim.x - 1 - (int)blockIdx.x;  // heavy tiles first
    const int h = blockIdx.y, b = blockIdx.z;
    const int q0 = qt * 64;

    const size_t bh = (size_t)(b * NHc + h) * Tc;
    const __nv_bfloat16* qhp = Qhi + (bh + q0) * HDc;
    const __nv_bfloat16* qlp = Qlo + (bh + q0) * HDc;
    const __nv_bfloat16* khp = Khi_g + bh * HDc;
    const __nv_bfloat16* klp = Klo_g + bh * HDc;
    const __nv_bfloat16* vhp = Vhi_g + bh * HDc;
    const __nv_bfloat16* vlp = Vlo_g + bh * HDc;

    auto buf = [&](int stg, int mat) -> uint32_t {
        return sbase + (uint32_t)(stg * 4 + mat) * ATB;
    };

    // kv tile: 4 mats x 64 rows x 8 segs = 2048 segs; 16 per thread
    auto load_kv = [&](int kt, int stg) {
        const int k0 = kt * 64;
        #pragma unroll
        for (int s = 0; s < 16; s++) {
            const int idx = s * 128 + tid;
            const int mat = idx >> 9;
            const int within = idx & 511;
            const int row = within >> 3;
            const int seg = within & 7;
            const __nv_bfloat16* src =
                (mat == 0 ? khp : mat == 1 ? klp : mat == 2 ? vhp : vlp) +
                (size_t)(k0 + row) * HDc + seg * 8;
            cp_async16_s(buf(stg, mat) + (uint32_t)(row * ALD + seg * 8) * 2, src);
        }
        cp_commit();
    };

    // ---- stage Q (64x64 hi/lo) into stage-1 buffers 0,1 ----------------------
    {
        #pragma unroll
        for (int s = 0; s < 8; s++) {
            const int idx = s * 128 + tid;      // 0..1023
            const int matq = idx >> 9;          // 0=hi,1=lo
            const int within = idx & 511;
            const int row = within >> 3;
            const int seg = within & 7;
            const __nv_bfloat16* src = (matq ? qlp : qhp) + (size_t)row * HDc + seg * 8;
            cp_async16_s(buf(1, matq) + (uint32_t)(row * ALD + seg * 8) * 2, src);
        }
        cp_commit();
    }
    load_kv(0, 0);
    cp_wait<1>();      // Q staged (kv tile0 may still be in flight)
    __syncthreads();

    // ---- persistent Q fragments ----------------------------------------------
    uint32_t qh[4][4], ql[4][4];
    {
        const int qrow = w * 16;
        const uint32_t hb = buf(1, 0);
        const uint32_t lb = buf(1, 1);
        const int arow = (lane & 7) + ((lane >> 3) & 1) * 8;
        const int acol = (lane >> 4) * 8;
        #pragma unroll
        for (int ks = 0; ks < 4; ks++) {
            ldsm4(qh[ks], hb + (uint32_t)((qrow + arow) * ALD + ks * 16 + acol) * 2);
            ldsm4(ql[ks], lb + (uint32_t)((qrow + arow) * ALD + ks * 16 + acol) * 2);
        }
    }

    float oacc[8][4];
    #pragma unroll
    for (int j = 0; j < 8; j++)
        #pragma unroll
        for (int e = 0; e < 4; e++) oacc[j][e] = 0.0f;
    float m0 = -1e30f, m1 = -1e30f, l0 = 0.0f, l1 = 0.0f;

    const int qrow0 = q0 + w * 16 + g;
    const int qrow1 = qrow0 + 8;
    const int nkt = qt + 1;

    const int b_nrow = (lane & 7) + (lane >> 4) * 8;
    const int b_kcol = ((lane >> 3) & 1) * 8;
    const int v_krow = (lane & 7) + ((lane >> 3) & 1) * 8;
    const int v_ncol = (lane >> 4) * 8;

    for (int kt = 0; kt < nkt; kt++) {
        cp_wait<0>();
        __syncthreads();
        if (kt + 1 < nkt) load_kv(kt + 1, (kt + 1) & 1);
        const int stg = kt & 1;
        const uint32_t kh_b = buf(stg, 0), kl_b = buf(stg, 1);
        const uint32_t vh_b = buf(stg, 2), vl_b = buf(stg, 3);

        // ---- S = Q K^T -------------------------------------------------------
        float sacc[8][4];
        #pragma unroll
        for (int j = 0; j < 8; j++)
            #pragma unroll
            for (int e = 0; e < 4; e++) sacc[j][e] = 0.0f;

        #pragma unroll
        for (int ks = 0; ks < 4; ks++) {
            #pragma unroll
            for (int p = 0; p < 4; p++) {
                const uint32_t off =
                    (uint32_t)((p * 16 + b_nrow) * ALD + ks * 16 + b_kcol) * 2;
                uint32_t kh4[4], kl4[4];
                ldsm4(kh4, kh_b + off);
                ldsm4(kl4, kl_b + off);
                mma_bf16(sacc[2 * p + 0], qh[ks], kh4[0], kh4[1]);
                mma_bf16(sacc[2 * p + 0], qh[ks], kl4[0], kl4[1]);
                mma_bf16(sacc[2 * p + 0], ql[ks], kh4[0], kh4[1]);
                mma_bf16(sacc[2 * p + 1], qh[ks], kh4[2], kh4[3]);
                mma_bf16(sacc[2 * p + 1], qh[ks], kl4[2], kl4[3]);
                mma_bf16(sacc[2 * p + 1], ql[ks], kh4[2], kh4[3]);
            }
        }

        // ---- mask (diagonal tile only) + online softmax ------------------------
        if (kt == qt) {
            #pragma unroll
            for (int j = 0; j < 8; j++) {
                const int kc = kt * 64 + j * 8 + t * 2;
                if (kc     > qrow0) sacc[j][0] = -1e30f;
                if (kc + 1 > qrow0) sacc[j][1] = -1e30f;
                if (kc     > qrow1) sacc[j][2] = -1e30f;
                if (kc + 1 > qrow1) sacc[j][3] = -1e30f;
            }
        }
        float mx0 = -1e30f, mx1 = -1e30f;
        #pragma unroll
        for (int j = 0; j < 8; j++) {
            mx0 = fmaxf(mx0, fmaxf(sacc[j][0], sacc[j][1]));
            mx1 = fmaxf(mx1, fmaxf(sacc[j][2], sacc[j][3]));
        }
        mx0 = fmaxf(mx0, __shfl_xor_sync(0xffffffffu, mx0, 1));
        mx0 = fmaxf(mx0, __shfl_xor_sync(0xffffffffu, mx0, 2));
        mx1 = fmaxf(mx1, __shfl_xor_sync(0xffffffffu, mx1, 1));
        mx1 = fmaxf(mx1, __shfl_xor_sync(0xffffffffu, mx1, 2));

        const float mn0 = fmaxf(m0, mx0), mn1 = fmaxf(m1, mx1);
        const float c0 = exp2f(m0 - mn0), c1 = exp2f(m1 - mn1);
        m0 = mn0; m1 = mn1;

        uint32_t pah[8][2], pal[8][2];
        float s0 = 0.0f, s1 = 0.0f;
        #pragma unroll
        for (int j = 0; j < 8; j++) {
            const float p0 = exp2f(sacc[j][0] - mn0);
            const float p1 = exp2f(sacc[j][1] - mn0);
            const float p2 = exp2f(sacc[j][2] - mn1);
            const float p3 = exp2f(sacc[j][3] - mn1);
            s0 += p0 + p1; s1 += p2 + p3;
            const float h0 = __bfloat162float(__float2bfloat16(p0));
            const float h1 = __bfloat162float(__float2bfloat16(p1));
            const float h2 = __bfloat162float(__float2bfloat16(p2));
            const float h3 = __bfloat162float(__float2bfloat16(p3));
            pah[j][0] = pack_bf16(h0, h1);
            pah[j][1] = pack_bf16(h2, h3);
            pal[j][0] = pack_bf16(p0 - h0, p1 - h1);
            pal[j][1] = pack_bf16(p2 - h2, p3 - h3);
        }
        l0 = l0 * c0 + s0;
        l1 = l1 * c1 + s1;
        #pragma unroll
        for (int j = 0; j < 8; j++) {
            oacc[j][0] *= c0; oacc[j][1] *= c0;
            oacc[j][2] *= c1; oacc[j][3] *= c1;
        }

        // ---- O += P V  (full bf16x3) -------------------------------------------
        #pragma unroll
        for (int ks = 0; ks < 4; ks++) {
            uint32_t afh[4] = {pah[2 * ks][0], pah[2 * ks][1],
                               pah[2 * ks + 1][0], pah[2 * ks + 1][1]};
            uint32_t afl[4] = {pal[2 * ks][0], pal[2 * ks][1],
                               pal[2 * ks + 1][0], pal[2 * ks + 1][1]};
            #pragma unroll
            for (int p = 0; p < 4; p++) {
                const uint32_t off =
                    (uint32_t)((ks * 16 + v_krow) * ALD + p * 16 + v_ncol) * 2;
                uint32_t vh4[4], vl4[4];
                ldsm4t(vh4, vh_b + off);
                ldsm4t(vl4, vl_b + off);
                mma_bf16(oacc[2 * p + 0], afh, vh4[0], vh4[1]);
                mma_bf16(oacc[2 * p + 0], afh, vl4[0], vl4[1]);
                mma_bf16(oacc[2 * p + 0], afl, vh4[0], vh4[1]);
                mma_bf16(oacc[2 * p + 1], afh, vh4[2], vh4[3]);
                mma_bf16(oacc[2 * p + 1], afh, vl4[2], vl4[3]);
                mma_bf16(oacc[2 * p + 1], afl, vh4[2], vh4[3]);
            }
        }
    }

    l0 += __shfl_xor_sync(0xffffffffu, l0, 1);
    l0 += __shfl_xor_sync(0xffffffffu, l0, 2);
    l1 += __shfl_xor_sync(0xffffffffu, l1, 1);
    l1 += __shfl_xor_sync(0xffffffffu, l1, 2);
    const float i0 = 1.0f / l0, i1 = 1.0f / l1;

    const size_t y0 = ((size_t)b * Tc + qrow0) * Cc + h * HDc + t * 2;
    const size_t y1 = ((size_t)b * Tc + qrow1) * Cc + h * HDc + t * 2;
    #pragma unroll
    for (int j = 0; j < 8; j++) {
        const float f0 = oacc[j][0] * i0, f1 = oacc[j][1] * i0;
        const float f2 = oacc[j][2] * i1, f3 = oacc[j][3] * i1;
        const float h0 = __bfloat162float(__float2bfloat16(f0));
        const float h1 = __bfloat162float(__float2bfloat16(f1));
        const float h2 = __bfloat162float(__float2bfloat16(f2));
        const float h3 = __bfloat162float(__float2bfloat16(f3));
        *(uint32_t*)(Yhi + y0 + j * 8) = pack_bf16(h0, h1);
        *(uint32_t*)(Ylo + y0 + j * 8) = pack_bf16(f0 - h0, f1 - h1);
        *(uint32_t*)(Yhi + y1 + j * 8) = pack_bf16(h2, h3);
        *(uint32_t*)(Ylo + y1 + j * 8) = pack_bf16(f2 - h2, f3 - h3);
    }
}

// ---------------------------------------------------------------------------
extern "C" void kernel_launch(void* const* d_in, const int* in_sizes, int n_in,
                              void* d_out, int out_size)
{
    const float* x  = (const float*)d_in[0];
    const float* Wq = (const float*)d_in[1];
    const float* Wk = (const float*)d_in[2];
    const float* Wv = (const float*)d_in[3];
    const float* Wo = (const float*)d_in[4];
    float* out = (float*)d_out;

    __nv_bfloat16 *qhi, *qlo, *khi, *klo, *vhi, *vlo;
    __nv_bfloat16 *xhi, *xlo, *yhi, *ylo, *whi, *wlo;
    cudaGetSymbolAddress((void**)&qhi, g_qhi);
    cudaGetSymbolAddress((void**)&qlo, g_qlo);
    cudaGetSymbolAddress((void**)&khi, g_khi);
    cudaGetSymbolAddress((void**)&klo, g_klo);
    cudaGetSymbolAddress((void**)&vhi, g_vhi);
    cudaGetSymbolAddress((void**)&vlo, g_vlo);
    cudaGetSymbolAddress((void**)&xhi, g_xhi);
    cudaGetSymbolAddress((void**)&xlo, g_xlo);
    cudaGetSymbolAddress((void**)&yhi, g_yhi);
    cudaGetSymbolAddress((void**)&ylo, g_ylo);
    cudaGetSymbolAddress((void**)&whi, g_whi);
    cudaGetSymbolAddress((void**)&wlo, g_wlo);

    const int M = Bc * Tc;       // 4096
    const int NELX = M * Cc;     // 4 M
    const int NELW = Cc * Cc;    // 1 M

    split_kernel<<<(NELX / 4 + 255) / 256, 256>>>(x, xhi, xlo, NELX / 4);
    split4_kernel<<<(4 * NELW / 4) / 256, 256>>>(Wq, Wk, Wv, Wo, whi, wlo);

    cudaFuncSetAttribute(gemm_mma_kernel<0>,
                         cudaFuncAttributeMaxDynamicSharedMemorySize, GSMEM_BYTES);
    cudaFuncSetAttribute(gemm_mma_kernel<1>,
                         cudaFuncAttributeMaxDynamicSharedMemorySize, GSMEM_BYTES);

    // Fused QKV projection: N = 3072 (Wq|Wk|Wv contiguous in g_whi/g_wlo)
    gemm_mma_kernel<1><<<dim3(3 * Cc / 128, M / 128), 256, GSMEM_BYTES>>>(
        xhi, xlo, whi, wlo, nullptr, 3 * Cc,
        qhi, qlo, khi, klo, vhi, vlo);

    cudaFuncSetAttribute(attn_fa2_kernel,
                         cudaFuncAttributeMaxDynamicSharedMemorySize, ASMEM_BYTES);
    attn_fa2_kernel<<<dim3(Tc / 64, NHc, Bc), 128, ASMEM_BYTES>>>(
        qhi, qlo, khi, klo, vhi, vlo, yhi, ylo);

    // Output projection: fp32 direct
    gemm_mma_kernel<0><<<dim3(Cc / 128, M / 128), 256, GSMEM_BYTES>>>(
        yhi, ylo, whi + 3 * NELW, wlo + 3 * NELW, out, Cc,
        nullptr, nullptr, nullptr, nullptr, nullptr, nullptr);
}